// round 1
// baseline (speedup 1.0000x reference)
#include <cuda_runtime.h>
#include <cuda_bf16.h>

#define U_    339
#define S_    5825
#define N_    6164
#define D_    128
#define H_    64
#define NNZ2_ 400000
#define B_    500000
#define EPS_  1e-5f

// ---------------- device scratch (static, no allocs) ----------------
__device__ float g_embA[N_ * D_];
__device__ float g_embB[N_ * D_];
__device__ int   g_cnt[N_];
__device__ int   g_cnt2[N_];
__device__ int   g_rowptr[N_ + 1];
__device__ int   g_colidx[NNZ2_];
__device__ float g_vals[NNZ2_];
__device__ float g_Q[2 * 128 * 64];   // [side][a][j]
__device__ float g_AB[N_ * H_];       // rows [0,U): A (+b1), rows [U,N): Bm

// ---------------- f32x2 helpers ----------------
__device__ __forceinline__ unsigned long long pack2(float lo, float hi) {
    unsigned long long r;
    asm("mov.b64 %0, {%1, %2};" : "=l"(r) : "f"(lo), "f"(hi));
    return r;
}
__device__ __forceinline__ void unpack2(unsigned long long v, float &lo, float &hi) {
    asm("mov.b64 {%0, %1}, %2;" : "=f"(lo), "=f"(hi) : "l"(v));
}
__device__ __forceinline__ void fma2(unsigned long long &d, unsigned long long a,
                                     unsigned long long b) {
    asm("fma.rn.f32x2 %0, %1, %2, %3;" : "=l"(d) : "l"(a), "l"(b), "l"(d));
}

// ---------------- K0: copy embeds, zero counters ----------------
__global__ void prep_kernel(const float* __restrict__ uE, const float* __restrict__ iE) {
    int i = blockIdx.x * blockDim.x + threadIdx.x;
    const int total = N_ * D_;
    for (int t = i; t < total; t += gridDim.x * blockDim.x) {
        g_embA[t] = (t < U_ * D_) ? uE[t] : iE[t - U_ * D_];
    }
    if (i < N_) { g_cnt[i] = 0; g_cnt2[i] = 0; }
}

// ---------------- K1: row histogram ----------------
__global__ void hist_kernel(const int* __restrict__ rows) {
    int i = blockIdx.x * blockDim.x + threadIdx.x;
    if (i < NNZ2_) atomicAdd(&g_cnt[rows[i]], 1);
}

// ---------------- K2: exclusive scan -> rowptr (single block, 1024 thr) ----------------
#define SCAN_CH 7
__global__ void scan_kernel() {
    __shared__ int sh[1024];
    int t = threadIdx.x;
    int base = t * SCAN_CH;
    int v[SCAN_CH];
    int s = 0;
#pragma unroll
    for (int q = 0; q < SCAN_CH; q++) {
        int idx = base + q;
        int c = (idx < N_) ? g_cnt[idx] : 0;
        v[q] = s;
        s += c;
    }
    sh[t] = s;
    __syncthreads();
    for (int off = 1; off < 1024; off <<= 1) {
        int add = (t >= off) ? sh[t - off] : 0;
        __syncthreads();
        sh[t] += add;
        __syncthreads();
    }
    int excl = (t == 0) ? 0 : sh[t - 1];
#pragma unroll
    for (int q = 0; q < SCAN_CH; q++) {
        int idx = base + q;
        if (idx < N_) g_rowptr[idx] = excl + v[q];
    }
    if (t == 0) g_rowptr[N_] = NNZ2_;
}

// ---------------- K3: scatter into CSR ----------------
__global__ void scatter_kernel(const int* __restrict__ rows, const int* __restrict__ cols,
                               const float* __restrict__ vals) {
    int i = blockIdx.x * blockDim.x + threadIdx.x;
    if (i < NNZ2_) {
        int r = rows[i];
        int pos = g_rowptr[r] + atomicAdd(&g_cnt2[r], 1);
        g_colidx[pos] = cols[i];
        g_vals[pos] = vals[i];
    }
}

// ---------------- K4: CSR SpMM, warp per row, float4 lanes ----------------
__global__ void spmm_kernel(int dir) {
    const float* __restrict__ in = dir ? g_embB : g_embA;
    float* __restrict__ out = dir ? g_embA : g_embB;
    int gw = (blockIdx.x * blockDim.x + threadIdx.x) >> 5;
    int lane = threadIdx.x & 31;
    if (gw >= N_) return;
    int beg = g_rowptr[gw], end = g_rowptr[gw + 1];
    const float4* __restrict__ src = (const float4*)in;
    float4 a0 = {0.f, 0.f, 0.f, 0.f};
    float4 a1 = {0.f, 0.f, 0.f, 0.f};
    int e = beg;
    for (; e + 2 <= end; e += 2) {
        float v0 = g_vals[e],     v1 = g_vals[e + 1];
        int   c0 = g_colidx[e],   c1 = g_colidx[e + 1];
        float4 t0 = src[c0 * 32 + lane];
        float4 t1 = src[c1 * 32 + lane];
        a0.x += v0 * t0.x; a0.y += v0 * t0.y; a0.z += v0 * t0.z; a0.w += v0 * t0.w;
        a1.x += v1 * t1.x; a1.y += v1 * t1.y; a1.z += v1 * t1.z; a1.w += v1 * t1.w;
    }
    if (e < end) {
        float v0 = g_vals[e];
        int c0 = g_colidx[e];
        float4 t0 = src[c0 * 32 + lane];
        a0.x += v0 * t0.x; a0.y += v0 * t0.y; a0.z += v0 * t0.z; a0.w += v0 * t0.w;
    }
    a0.x += a1.x; a0.y += a1.y; a0.z += a1.z; a0.w += a1.w;
    ((float4*)out)[gw * 32 + lane] = a0;
}

// ---------------- K5: Q[side] = H^T (H @ W1_half)  [128,64] ----------------
__global__ void hyperQ_kernel(const float* __restrict__ uH, const float* __restrict__ iH,
                              const float* __restrict__ W1) {
    int side = blockIdx.x;
    const float* __restrict__ Hp = side ? iH : uH;
    const float* __restrict__ W1p = W1 + side * 128 * 64;
    __shared__ float sH[32 * 128];
    __shared__ float sRW[32 * 64];
    int tid = threadIdx.x;
    for (int t = tid; t < 32 * 128; t += 256) sH[t] = Hp[t];
    __syncthreads();
    // RW[r][j] = sum_b H[r][b] * W1p[b][j]
    for (int o = tid; o < 32 * 64; o += 256) {
        int r = o >> 6, j = o & 63;
        float acc = 0.f;
        for (int b = 0; b < 128; b++) acc += sH[r * 128 + b] * W1p[b * 64 + j];
        sRW[o] = acc;
    }
    __syncthreads();
    // Q[a][j] = sum_r H[r][a] * RW[r][j]
    for (int o = tid; o < 128 * 64; o += 256) {
        int a = o >> 6, j = o & 63;
        float acc = 0.f;
#pragma unroll
        for (int r = 0; r < 32; r++) acc += sH[r * 128 + a] * sRW[r * 64 + j];
        g_Q[side * 128 * 64 + o] = acc;
    }
}

// ---------------- K6: AB = e3 @ Q(side)  (+b1 on user rows) ----------------
__global__ void projAB_kernel(const float* __restrict__ b1) {
    int rb = blockIdx.x * 32;
    __shared__ float sE[32 * 128];
    int tid = threadIdx.x;
    for (int t = tid; t < 32 * 128; t += 256) {
        int r = rb + (t >> 7);
        sE[t] = (r < N_) ? g_embB[r * 128 + (t & 127)] : 0.f;
    }
    __syncthreads();
    int j = tid & 63;
    int rl0 = tid >> 6;
    for (int rl = rl0; rl < 32; rl += 4) {
        int r = rb + rl;
        if (r >= N_) break;
        const float* __restrict__ Qp = (r < U_) ? g_Q : (g_Q + 128 * 64);
        float acc = (r < U_) ? b1[j] : 0.f;
#pragma unroll 8
        for (int k = 0; k < 128; k++) acc += sE[rl * 128 + k] * Qp[k * 64 + j];
        g_AB[r * 64 + j] = acc;
    }
}

// ---------------- K7: fused MLP over B rows ----------------
__global__ void __launch_bounds__(256)
mlp_kernel(const int* __restrict__ uIdx, const int* __restrict__ sIdx,
           const float* __restrict__ g1, const float* __restrict__ be1,
           const float* __restrict__ W2, const float* __restrict__ b2,
           const float* __restrict__ g2, const float* __restrict__ be2,
           const float* __restrict__ W3, const float* __restrict__ b3,
           float* __restrict__ out) {
    __shared__ __align__(16) float sW2[64 * 64];
    __shared__ float sg1[64], sbe1[64], sg2[64], sbe2[64], sW3[64];
    __shared__ unsigned long long sB2[32];
    int tid = threadIdx.x;
    for (int t = tid; t < 64 * 64; t += 256) sW2[t] = W2[t];
    if (tid < 64) {
        sg1[tid] = g1[tid]; sbe1[tid] = be1[tid];
        sg2[tid] = g2[tid]; sbe2[tid] = be2[tid];
        sW3[tid] = W3[tid];
    }
    if (tid < 32) sB2[tid] = pack2(b2[2 * tid], b2[2 * tid + 1]);
    __syncthreads();

    int i = blockIdx.x * 256 + tid;
    if (i >= B_) return;
    int u = uIdx[i], s = sIdx[i];
    const float4* __restrict__ pa = (const float4*)(g_AB + u * H_);
    const float4* __restrict__ pb = (const float4*)(g_AB + (U_ + s) * H_);

    float x[64];
    float sum = 0.f;
#pragma unroll
    for (int q = 0; q < 16; q++) {
        float4 a = pa[q];
        float4 b = pb[q];
        float v0 = a.x + b.x, v1 = a.y + b.y, v2 = a.z + b.z, v3 = a.w + b.w;
        x[4 * q] = v0; x[4 * q + 1] = v1; x[4 * q + 2] = v2; x[4 * q + 3] = v3;
        sum += v0 + v1 + v2 + v3;
    }
    float mu = sum * (1.f / 64.f);
    float var = 0.f;
#pragma unroll
    for (int k = 0; k < 64; k++) { float d = x[k] - mu; var += d * d; }
    float inv = rsqrtf(var * (1.f / 64.f) + EPS_);
#pragma unroll
    for (int k = 0; k < 64; k++)
        x[k] = fmaxf(0.f, (x[k] - mu) * inv * sg1[k] + sbe1[k]);

    // layer 2: y = x @ W2 via packed f32x2 FMA, W2 broadcast from smem
    unsigned long long y2[32];
#pragma unroll
    for (int q = 0; q < 32; q++) y2[q] = sB2[q];
#pragma unroll
    for (int k = 0; k < 64; k++) {
        unsigned long long xk2 = pack2(x[k], x[k]);
        const ulonglong2* __restrict__ wr = (const ulonglong2*)&sW2[k * 64];
#pragma unroll
        for (int q = 0; q < 16; q++) {
            ulonglong2 w = wr[q];
            fma2(y2[2 * q], xk2, w.x);
            fma2(y2[2 * q + 1], xk2, w.y);
        }
    }

    // LN2 + relu + dot W3
    float sum2 = 0.f;
#pragma unroll
    for (int q = 0; q < 32; q++) {
        float lo, hi;
        unpack2(y2[q], lo, hi);
        x[2 * q] = lo; x[2 * q + 1] = hi;
        sum2 += lo + hi;
    }
    float mu2 = sum2 * (1.f / 64.f);
    float var2 = 0.f;
#pragma unroll
    for (int k = 0; k < 64; k++) { float d = x[k] - mu2; var2 += d * d; }
    float inv2 = rsqrtf(var2 * (1.f / 64.f) + EPS_);
    float acc = 0.f;
#pragma unroll
    for (int k = 0; k < 64; k++) {
        float h = fmaxf(0.f, (x[k] - mu2) * inv2 * sg2[k] + sbe2[k]);
        acc += h * sW3[k];
    }
    out[i] = acc + b3[0];
}

// ---------------- launcher ----------------
extern "C" void kernel_launch(void* const* d_in, const int* in_sizes, int n_in,
                              void* d_out, int out_size) {
    const float* uE  = (const float*)d_in[0];
    const float* iE  = (const float*)d_in[1];
    const float* uH  = (const float*)d_in[2];
    const float* iH  = (const float*)d_in[3];
    const float* W1  = (const float*)d_in[4];
    const float* b1  = (const float*)d_in[5];
    const float* g1  = (const float*)d_in[6];
    const float* be1 = (const float*)d_in[7];
    const float* W2  = (const float*)d_in[8];
    const float* b2  = (const float*)d_in[9];
    const float* g2  = (const float*)d_in[10];
    const float* be2 = (const float*)d_in[11];
    const float* W3  = (const float*)d_in[12];
    const float* b3  = (const float*)d_in[13];
    const float* adj_vals = (const float*)d_in[14];
    const int*   adj_rows = (const int*)d_in[15];
    const int*   adj_cols = (const int*)d_in[16];
    const int*   uIdx = (const int*)d_in[17];
    const int*   sIdx = (const int*)d_in[18];
    float* out = (float*)d_out;

    prep_kernel<<<(N_ * D_ + 255) / 256, 256>>>(uE, iE);
    hist_kernel<<<(NNZ2_ + 255) / 256, 256>>>(adj_rows);
    scan_kernel<<<1, 1024>>>();
    scatter_kernel<<<(NNZ2_ + 255) / 256, 256>>>(adj_rows, adj_cols, adj_vals);
    spmm_kernel<<<(N_ * 32 + 255) / 256, 256>>>(0);   // A -> B
    spmm_kernel<<<(N_ * 32 + 255) / 256, 256>>>(1);   // B -> A
    spmm_kernel<<<(N_ * 32 + 255) / 256, 256>>>(0);   // A -> B  (e3 in g_embB)
    hyperQ_kernel<<<2, 256>>>(uH, iH, W1);
    projAB_kernel<<<(N_ + 31) / 32, 256>>>(b1);
    mlp_kernel<<<(B_ + 255) / 256, 256>>>(uIdx, sIdx, g1, be1, W2, b2, g2, be2, W3, b3, out);
}

// round 2
// speedup vs baseline: 1.8615x; 1.8615x over previous
#include <cuda_runtime.h>
#include <cuda_bf16.h>

#define U_    339
#define S_    5825
#define N_    6164
#define D_    128
#define H_    64
#define NNZ2_ 400000
#define B_    500000
#define EPS_  1e-5f

// ---------------- device scratch (static, no allocs) ----------------
__device__ float g_embA[N_ * D_];
__device__ float g_embB[N_ * D_];
__device__ int   g_cnt[N_];
__device__ int   g_cursor[N_];
__device__ int   g_rowptr[N_ + 1];
__device__ int   g_colidx[NNZ2_];
__device__ float g_vals[NNZ2_];
__device__ float g_Q[2 * 128 * 64];   // [side][a][j]
__device__ float g_AB[N_ * H_];       // rows [0,U): A (+b1), rows [U,N): B-side

// ---------------- f32x2 helpers ----------------
__device__ __forceinline__ unsigned long long pack2(float lo, float hi) {
    unsigned long long r;
    asm("mov.b64 %0, {%1, %2};" : "=l"(r) : "f"(lo), "f"(hi));
    return r;
}
__device__ __forceinline__ void unpack2(unsigned long long v, float &lo, float &hi) {
    asm("mov.b64 {%0, %1}, %2;" : "=f"(lo), "=f"(hi) : "l"(v));
}
__device__ __forceinline__ void fma2(unsigned long long &d, unsigned long long a,
                                     unsigned long long b) {
    asm("fma.rn.f32x2 %0, %1, %2, %3;" : "=l"(d) : "l"(a), "l"(b), "l"(d));
}

// ---------------- K0: copy embeds, zero counters ----------------
__global__ void prep_kernel(const float* __restrict__ uE, const float* __restrict__ iE) {
    int i = blockIdx.x * blockDim.x + threadIdx.x;
    const int total = N_ * D_;
    for (int t = i; t < total; t += gridDim.x * blockDim.x) {
        g_embA[t] = (t < U_ * D_) ? uE[t] : iE[t - U_ * D_];
    }
    if (i < N_) g_cnt[i] = 0;
}

// ---------------- K1: row histogram (block-local smem, then spread flush) ----------------
#define HBLKS 148
#define HTHREADS 512
#define HCHUNK ((NNZ2_ + HBLKS - 1) / HBLKS)   // 2703
__global__ void hist_kernel(const int* __restrict__ rows) {
    __shared__ int sc[N_];
    for (int t = threadIdx.x; t < N_; t += HTHREADS) sc[t] = 0;
    __syncthreads();
    int start = blockIdx.x * HCHUNK;
    int end = start + HCHUNK; if (end > NNZ2_) end = NNZ2_;
    for (int i = start + threadIdx.x; i < end; i += HTHREADS)
        atomicAdd(&sc[rows[i]], 1);
    __syncthreads();
    for (int t = threadIdx.x; t < N_; t += HTHREADS) {
        int c = sc[t];
        if (c) atomicAdd(&g_cnt[t], c);
    }
}

// ---------------- K2: exclusive scan -> rowptr + cursor (single block) ----------------
#define SCAN_CH 7
__global__ void scan_kernel() {
    __shared__ int sh[1024];
    int t = threadIdx.x;
    int base = t * SCAN_CH;
    int v[SCAN_CH];
    int s = 0;
#pragma unroll
    for (int q = 0; q < SCAN_CH; q++) {
        int idx = base + q;
        int c = (idx < N_) ? g_cnt[idx] : 0;
        v[q] = s;
        s += c;
    }
    sh[t] = s;
    __syncthreads();
    for (int off = 1; off < 1024; off <<= 1) {
        int add = (t >= off) ? sh[t - off] : 0;
        __syncthreads();
        sh[t] += add;
        __syncthreads();
    }
    int excl = (t == 0) ? 0 : sh[t - 1];
#pragma unroll
    for (int q = 0; q < SCAN_CH; q++) {
        int idx = base + q;
        if (idx < N_) {
            int p = excl + v[q];
            g_rowptr[idx] = p;
            g_cursor[idx] = p;
        }
    }
    if (t == 0) g_rowptr[N_] = NNZ2_;
}

// ---------------- K3: scatter into CSR (block-local positions + per-row reservation) ----------------
#define SQ 6   // ceil(2703 / 512)
__global__ void scatter_kernel(const int* __restrict__ rows, const int* __restrict__ cols,
                               const float* __restrict__ vals) {
    __shared__ int sc[N_];
    for (int t = threadIdx.x; t < N_; t += HTHREADS) sc[t] = 0;
    __syncthreads();
    int start = blockIdx.x * HCHUNK;
    int end = start + HCHUNK; if (end > NNZ2_) end = NNZ2_;

    int myrow[SQ], mycol[SQ], mypos[SQ];
    float myval[SQ];
#pragma unroll
    for (int q = 0; q < SQ; q++) {
        int i = start + q * HTHREADS + threadIdx.x;
        bool valid = (i < end);
        int r = valid ? rows[i] : 0;
        myrow[q] = valid ? r : -1;
        mycol[q] = valid ? cols[i] : 0;
        myval[q] = valid ? vals[i] : 0.f;
        mypos[q] = valid ? atomicAdd(&sc[r], 1) : 0;
    }
    __syncthreads();
    // reserve global range per row present in this block; reuse sc for bases
    for (int t = threadIdx.x; t < N_; t += HTHREADS) {
        int c = sc[t];
        if (c) sc[t] = atomicAdd(&g_cursor[t], c);
    }
    __syncthreads();
#pragma unroll
    for (int q = 0; q < SQ; q++) {
        if (myrow[q] >= 0) {
            int p = sc[myrow[q]] + mypos[q];
            g_colidx[p] = mycol[q];
            g_vals[p] = myval[q];
        }
    }
}

// ---------------- K4: CSR SpMM, load-balanced ----------------
// blocks [0,U_): one block per user row (deg ~590), 8 warps split edges
// blocks [U_, U_+ceil(S_/8)): 8 service rows per block, warp-per-row
#define SPMM_SBLKS ((S_ + 7) / 8)
__global__ void spmm_kernel(int dir) {
    const float* __restrict__ in = dir ? g_embB : g_embA;
    float* __restrict__ out = dir ? g_embA : g_embB;
    const float4* __restrict__ src = (const float4*)in;
    int lane = threadIdx.x & 31;
    int w = threadIdx.x >> 5;

    if (blockIdx.x < U_) {
        int row = blockIdx.x;
        int beg = g_rowptr[row], end = g_rowptr[row + 1];
        float4 a = {0.f, 0.f, 0.f, 0.f};
        for (int e = beg + w; e < end; e += 8) {
            float v = g_vals[e];
            int c = g_colidx[e];
            float4 t = src[c * 32 + lane];
            a.x += v * t.x; a.y += v * t.y; a.z += v * t.z; a.w += v * t.w;
        }
        __shared__ float4 red[256];
        int tid = threadIdx.x;
        red[tid] = a; __syncthreads();
        if (tid < 128) {
            float4 b = red[tid + 128];
            a.x += b.x; a.y += b.y; a.z += b.z; a.w += b.w;
            red[tid] = a;
        }
        __syncthreads();
        if (tid < 64) {
            float4 b = red[tid + 64];
            a.x += b.x; a.y += b.y; a.z += b.z; a.w += b.w;
            red[tid] = a;
        }
        __syncthreads();
        if (tid < 32) {
            float4 b = red[tid + 32];
            a.x += b.x; a.y += b.y; a.z += b.z; a.w += b.w;
            ((float4*)out)[row * 32 + lane] = a;
        }
    } else {
        int row = U_ + (blockIdx.x - U_) * 8 + w;
        if (row >= N_) return;
        int beg = g_rowptr[row], end = g_rowptr[row + 1];
        float4 a0 = {0.f, 0.f, 0.f, 0.f};
        float4 a1 = {0.f, 0.f, 0.f, 0.f};
        int e = beg;
        for (; e + 2 <= end; e += 2) {
            float v0 = g_vals[e],   v1 = g_vals[e + 1];
            int   c0 = g_colidx[e], c1 = g_colidx[e + 1];
            float4 t0 = src[c0 * 32 + lane];
            float4 t1 = src[c1 * 32 + lane];
            a0.x += v0 * t0.x; a0.y += v0 * t0.y; a0.z += v0 * t0.z; a0.w += v0 * t0.w;
            a1.x += v1 * t1.x; a1.y += v1 * t1.y; a1.z += v1 * t1.z; a1.w += v1 * t1.w;
        }
        if (e < end) {
            float v0 = g_vals[e];
            int c0 = g_colidx[e];
            float4 t0 = src[c0 * 32 + lane];
            a0.x += v0 * t0.x; a0.y += v0 * t0.y; a0.z += v0 * t0.z; a0.w += v0 * t0.w;
        }
        a0.x += a1.x; a0.y += a1.y; a0.z += a1.z; a0.w += a1.w;
        ((float4*)out)[row * 32 + lane] = a0;
    }
}

// ---------------- K5: Q[side] = H^T (H @ W1_half)  [128,64] ----------------
__global__ void hyperQ_kernel(const float* __restrict__ uH, const float* __restrict__ iH,
                              const float* __restrict__ W1) {
    int side = blockIdx.x;
    const float* __restrict__ Hp = side ? iH : uH;
    const float* __restrict__ W1p = W1 + side * 128 * 64;
    __shared__ float sH[32 * 128];
    __shared__ float sRW[32 * 64];
    int tid = threadIdx.x;
    for (int t = tid; t < 32 * 128; t += 256) sH[t] = Hp[t];
    __syncthreads();
    for (int o = tid; o < 32 * 64; o += 256) {
        int r = o >> 6, j = o & 63;
        float acc = 0.f;
        for (int b = 0; b < 128; b++) acc += sH[r * 128 + b] * W1p[b * 64 + j];
        sRW[o] = acc;
    }
    __syncthreads();
    for (int o = tid; o < 128 * 64; o += 256) {
        int a = o >> 6, j = o & 63;
        float acc = 0.f;
#pragma unroll
        for (int r = 0; r < 32; r++) acc += sH[r * 128 + a] * sRW[r * 64 + j];
        g_Q[side * 128 * 64 + o] = acc;
    }
}

// ---------------- K6: AB = e3 @ Q(side)  (+b1 on user rows) ----------------
__global__ void projAB_kernel(const float* __restrict__ b1) {
    int rb = blockIdx.x * 32;
    __shared__ float sE[32 * 128];
    int tid = threadIdx.x;
    for (int t = tid; t < 32 * 128; t += 256) {
        int r = rb + (t >> 7);
        sE[t] = (r < N_) ? g_embB[r * 128 + (t & 127)] : 0.f;
    }
    __syncthreads();
    int j = tid & 63;
    int rl0 = tid >> 6;
    for (int rl = rl0; rl < 32; rl += 4) {
        int r = rb + rl;
        if (r >= N_) break;
        const float* __restrict__ Qp = (r < U_) ? g_Q : (g_Q + 128 * 64);
        float acc = (r < U_) ? b1[j] : 0.f;
#pragma unroll 8
        for (int k = 0; k < 128; k++) acc += sE[rl * 128 + k] * Qp[k * 64 + j];
        g_AB[r * 64 + j] = acc;
    }
}

// ---------------- K7: fused MLP over B rows ----------------
// x is staged through padded smem between LN1 and layer-2 so the x[64]
// register array dies before the y2[32] accumulators are born (no spills).
#define XSTR 65
__global__ void __launch_bounds__(256)
mlp_kernel(const int* __restrict__ uIdx, const int* __restrict__ sIdx,
           const float* __restrict__ g1, const float* __restrict__ be1,
           const float* __restrict__ W2, const float* __restrict__ b2,
           const float* __restrict__ g2, const float* __restrict__ be2,
           const float* __restrict__ W3, const float* __restrict__ b3,
           float* __restrict__ out) {
    extern __shared__ float sx[];                 // [256 * XSTR]
    __shared__ __align__(16) float sW2[64 * 64];
    __shared__ float sg1[64], sbe1[64], sg2[64], sbe2[64], sW3[64];
    __shared__ unsigned long long sB2[32];
    int tid = threadIdx.x;
    for (int t = tid; t < 64 * 64; t += 256) sW2[t] = W2[t];
    if (tid < 64) {
        sg1[tid] = g1[tid]; sbe1[tid] = be1[tid];
        sg2[tid] = g2[tid]; sbe2[tid] = be2[tid];
        sW3[tid] = W3[tid];
    }
    if (tid < 32) sB2[tid] = pack2(b2[2 * tid], b2[2 * tid + 1]);
    __syncthreads();

    int i = blockIdx.x * 256 + tid;
    if (i >= B_) return;
    int u = uIdx[i], s = sIdx[i];
    const float4* __restrict__ pa = (const float4*)(g_AB + u * H_);
    const float4* __restrict__ pb = (const float4*)(g_AB + (U_ + s) * H_);
    float* __restrict__ sxr = sx + tid * XSTR;

    // ---- phase 1: gather + LN1 + relu -> smem (x regs die here) ----
    {
        float x[64];
        float sum = 0.f;
#pragma unroll
        for (int q = 0; q < 16; q++) {
            float4 a = pa[q];
            float4 b = pb[q];
            float v0 = a.x + b.x, v1 = a.y + b.y, v2 = a.z + b.z, v3 = a.w + b.w;
            x[4 * q] = v0; x[4 * q + 1] = v1; x[4 * q + 2] = v2; x[4 * q + 3] = v3;
            sum += v0 + v1 + v2 + v3;
        }
        float mu = sum * (1.f / 64.f);
        float var = 0.f;
#pragma unroll
        for (int k = 0; k < 64; k++) { float d = x[k] - mu; var += d * d; }
        float inv = rsqrtf(var * (1.f / 64.f) + EPS_);
#pragma unroll
        for (int k = 0; k < 64; k++)
            sxr[k] = fmaxf(0.f, (x[k] - mu) * inv * sg1[k] + sbe1[k]);
    }

    // ---- phase 2: layer 2 via packed f32x2 FMA, W2 broadcast from smem ----
    unsigned long long y2[32];
#pragma unroll
    for (int q = 0; q < 32; q++) y2[q] = sB2[q];
#pragma unroll 4
    for (int k = 0; k < 64; k++) {
        float xk = sxr[k];
        unsigned long long xk2 = pack2(xk, xk);
        const ulonglong2* __restrict__ wr = (const ulonglong2*)&sW2[k * 64];
#pragma unroll
        for (int q = 0; q < 16; q++) {
            ulonglong2 w = wr[q];
            fma2(y2[2 * q], xk2, w.x);
            fma2(y2[2 * q + 1], xk2, w.y);
        }
    }

    // ---- phase 3: LN2 + relu + dot W3 ----
    float y[64];
    float sum2 = 0.f;
#pragma unroll
    for (int q = 0; q < 32; q++) {
        float lo, hi;
        unpack2(y2[q], lo, hi);
        y[2 * q] = lo; y[2 * q + 1] = hi;
        sum2 += lo + hi;
    }
    float mu2 = sum2 * (1.f / 64.f);
    float var2 = 0.f;
#pragma unroll
    for (int k = 0; k < 64; k++) { float d = y[k] - mu2; var2 += d * d; }
    float inv2 = rsqrtf(var2 * (1.f / 64.f) + EPS_);
    float acc = 0.f;
#pragma unroll
    for (int k = 0; k < 64; k++) {
        float h = fmaxf(0.f, (y[k] - mu2) * inv2 * sg2[k] + sbe2[k]);
        acc += h * sW3[k];
    }
    out[i] = acc + b3[0];
}

// ---------------- launcher ----------------
extern "C" void kernel_launch(void* const* d_in, const int* in_sizes, int n_in,
                              void* d_out, int out_size) {
    const float* uE  = (const float*)d_in[0];
    const float* iE  = (const float*)d_in[1];
    const float* uH  = (const float*)d_in[2];
    const float* iH  = (const float*)d_in[3];
    const float* W1  = (const float*)d_in[4];
    const float* b1  = (const float*)d_in[5];
    const float* g1  = (const float*)d_in[6];
    const float* be1 = (const float*)d_in[7];
    const float* W2  = (const float*)d_in[8];
    const float* b2  = (const float*)d_in[9];
    const float* g2  = (const float*)d_in[10];
    const float* be2 = (const float*)d_in[11];
    const float* W3  = (const float*)d_in[12];
    const float* b3  = (const float*)d_in[13];
    const float* adj_vals = (const float*)d_in[14];
    const int*   adj_rows = (const int*)d_in[15];
    const int*   adj_cols = (const int*)d_in[16];
    const int*   uIdx = (const int*)d_in[17];
    const int*   sIdx = (const int*)d_in[18];
    float* out = (float*)d_out;

    static int attr_set = 0;
    if (!attr_set) {
        cudaFuncSetAttribute(mlp_kernel, cudaFuncAttributeMaxDynamicSharedMemorySize,
                             256 * XSTR * 4);
        attr_set = 1;
    }

    prep_kernel<<<(N_ * D_ + 255) / 256, 256>>>(uE, iE);
    hist_kernel<<<HBLKS, HTHREADS>>>(adj_rows);
    scan_kernel<<<1, 1024>>>();
    scatter_kernel<<<HBLKS, HTHREADS>>>(adj_rows, adj_cols, adj_vals);
    spmm_kernel<<<U_ + SPMM_SBLKS, 256>>>(0);   // A -> B
    spmm_kernel<<<U_ + SPMM_SBLKS, 256>>>(1);   // B -> A
    spmm_kernel<<<U_ + SPMM_SBLKS, 256>>>(0);   // A -> B  (e3 in g_embB)
    hyperQ_kernel<<<2, 256>>>(uH, iH, W1);
    projAB_kernel<<<(N_ + 31) / 32, 256>>>(b1);
    mlp_kernel<<<(B_ + 255) / 256, 256, 256 * XSTR * 4>>>(uIdx, sIdx, g1, be1, W2, b2,
                                                          g2, be2, W3, b3, out);
}

// round 4
// speedup vs baseline: 2.4372x; 1.3093x over previous
#include <cuda_runtime.h>
#include <cuda_bf16.h>
#include <cstdint>

#define U_    339
#define S_    5825
#define N_    6164
#define D_    128
#define H_    64
#define NNZ2_ 400000
#define B_    500000
#define EPS_  1e-5f

// ---------------- device scratch (static, no allocs) ----------------
__device__ float g_embA[N_ * D_];
__device__ float g_embB[N_ * D_];
__device__ int   g_cnt[N_];
__device__ int   g_cursor[N_];
__device__ int   g_rowptr[N_ + 1];
__device__ int   g_colidx[NNZ2_];
__device__ float g_vals[NNZ2_];
__device__ float g_Q[2 * 128 * 64];   // [side][a][j]
__device__ float g_AB[N_ * H_];       // rows [0,U): A (+b1), rows [U,N): B-side

// ---------------- helpers ----------------
__device__ __forceinline__ uint32_t to_tf32(float f) {
    uint32_t r;
    asm("cvt.rna.tf32.f32 %0, %1;" : "=r"(r) : "f"(f));
    return r;
}
__device__ __forceinline__ void mma16n8k8(float c[4], uint32_t a0, uint32_t a1,
                                          uint32_t a2, uint32_t a3,
                                          uint32_t b0, uint32_t b1) {
    asm volatile(
        "mma.sync.aligned.m16n8k8.row.col.f32.tf32.tf32.f32 "
        "{%0,%1,%2,%3}, {%4,%5,%6,%7}, {%8,%9}, {%0,%1,%2,%3};"
        : "+f"(c[0]), "+f"(c[1]), "+f"(c[2]), "+f"(c[3])
        : "r"(a0), "r"(a1), "r"(a2), "r"(a3), "r"(b0), "r"(b1));
}

// ---------------- K0: copy embeds, zero counters ----------------
__global__ void prep_kernel(const float* __restrict__ uE, const float* __restrict__ iE) {
    int i = blockIdx.x * blockDim.x + threadIdx.x;
    const int total = N_ * D_;
    for (int t = i; t < total; t += gridDim.x * blockDim.x) {
        g_embA[t] = (t < U_ * D_) ? uE[t] : iE[t - U_ * D_];
    }
    if (i < N_) g_cnt[i] = 0;
}

// ---------------- K1: row histogram (block-local smem, then spread flush) ----------------
#define HBLKS 148
#define HTHREADS 512
#define HCHUNK ((NNZ2_ + HBLKS - 1) / HBLKS)   // 2703
__global__ void hist_kernel(const int* __restrict__ rows) {
    __shared__ int sc[N_];
    for (int t = threadIdx.x; t < N_; t += HTHREADS) sc[t] = 0;
    __syncthreads();
    int start = blockIdx.x * HCHUNK;
    int end = start + HCHUNK; if (end > NNZ2_) end = NNZ2_;
    for (int i = start + threadIdx.x; i < end; i += HTHREADS)
        atomicAdd(&sc[rows[i]], 1);
    __syncthreads();
    for (int t = threadIdx.x; t < N_; t += HTHREADS) {
        int c = sc[t];
        if (c) atomicAdd(&g_cnt[t], c);
    }
}

// ---------------- K2: exclusive scan -> rowptr + cursor (single block) ----------------
#define SCAN_CH 7
__global__ void scan_kernel() {
    __shared__ int sh[1024];
    int t = threadIdx.x;
    int base = t * SCAN_CH;
    int v[SCAN_CH];
    int s = 0;
#pragma unroll
    for (int q = 0; q < SCAN_CH; q++) {
        int idx = base + q;
        int c = (idx < N_) ? g_cnt[idx] : 0;
        v[q] = s;
        s += c;
    }
    sh[t] = s;
    __syncthreads();
    for (int off = 1; off < 1024; off <<= 1) {
        int add = (t >= off) ? sh[t - off] : 0;
        __syncthreads();
        sh[t] += add;
        __syncthreads();
    }
    int excl = (t == 0) ? 0 : sh[t - 1];
#pragma unroll
    for (int q = 0; q < SCAN_CH; q++) {
        int idx = base + q;
        if (idx < N_) {
            int p = excl + v[q];
            g_rowptr[idx] = p;
            g_cursor[idx] = p;
        }
    }
    if (t == 0) g_rowptr[N_] = NNZ2_;
}

// ---------------- K3: scatter into CSR (block-local positions + per-row reservation) ----------------
#define SQ 6
__global__ void scatter_kernel(const int* __restrict__ rows, const int* __restrict__ cols,
                               const float* __restrict__ vals) {
    __shared__ int sc[N_];
    for (int t = threadIdx.x; t < N_; t += HTHREADS) sc[t] = 0;
    __syncthreads();
    int start = blockIdx.x * HCHUNK;
    int end = start + HCHUNK; if (end > NNZ2_) end = NNZ2_;

    int myrow[SQ], mycol[SQ], mypos[SQ];
    float myval[SQ];
#pragma unroll
    for (int q = 0; q < SQ; q++) {
        int i = start + q * HTHREADS + threadIdx.x;
        bool valid = (i < end);
        int r = valid ? rows[i] : 0;
        myrow[q] = valid ? r : -1;
        mycol[q] = valid ? cols[i] : 0;
        myval[q] = valid ? vals[i] : 0.f;
        mypos[q] = valid ? atomicAdd(&sc[r], 1) : 0;
    }
    __syncthreads();
    for (int t = threadIdx.x; t < N_; t += HTHREADS) {
        int c = sc[t];
        if (c) sc[t] = atomicAdd(&g_cursor[t], c);
    }
    __syncthreads();
#pragma unroll
    for (int q = 0; q < SQ; q++) {
        if (myrow[q] >= 0) {
            int p = sc[myrow[q]] + mypos[q];
            g_colidx[p] = mycol[q];
            g_vals[p] = myval[q];
        }
    }
}

// ---------------- K4: CSR SpMM, load-balanced ----------------
#define SPMM_SBLKS ((S_ + 7) / 8)
__global__ void spmm_kernel(int dir) {
    const float* __restrict__ in = dir ? g_embB : g_embA;
    float* __restrict__ out = dir ? g_embA : g_embB;
    const float4* __restrict__ src = (const float4*)in;
    int lane = threadIdx.x & 31;
    int w = threadIdx.x >> 5;

    if (blockIdx.x < U_) {
        int row = blockIdx.x;
        int beg = g_rowptr[row], end = g_rowptr[row + 1];
        float4 a = {0.f, 0.f, 0.f, 0.f};
        for (int e = beg + w; e < end; e += 8) {
            float v = g_vals[e];
            int c = g_colidx[e];
            float4 t = src[c * 32 + lane];
            a.x += v * t.x; a.y += v * t.y; a.z += v * t.z; a.w += v * t.w;
        }
        __shared__ float4 red[256];
        int tid = threadIdx.x;
        red[tid] = a; __syncthreads();
        if (tid < 128) {
            float4 b = red[tid + 128];
            a.x += b.x; a.y += b.y; a.z += b.z; a.w += b.w;
            red[tid] = a;
        }
        __syncthreads();
        if (tid < 64) {
            float4 b = red[tid + 64];
            a.x += b.x; a.y += b.y; a.z += b.z; a.w += b.w;
            red[tid] = a;
        }
        __syncthreads();
        if (tid < 32) {
            float4 b = red[tid + 32];
            a.x += b.x; a.y += b.y; a.z += b.z; a.w += b.w;
            ((float4*)out)[row * 32 + lane] = a;
        }
    } else {
        int row = U_ + (blockIdx.x - U_) * 8 + w;
        if (row >= N_) return;
        int beg = g_rowptr[row], end = g_rowptr[row + 1];
        float4 a0 = {0.f, 0.f, 0.f, 0.f};
        float4 a1 = {0.f, 0.f, 0.f, 0.f};
        int e = beg;
        for (; e + 2 <= end; e += 2) {
            float v0 = g_vals[e],   v1 = g_vals[e + 1];
            int   c0 = g_colidx[e], c1 = g_colidx[e + 1];
            float4 t0 = src[c0 * 32 + lane];
            float4 t1 = src[c1 * 32 + lane];
            a0.x += v0 * t0.x; a0.y += v0 * t0.y; a0.z += v0 * t0.z; a0.w += v0 * t0.w;
            a1.x += v1 * t1.x; a1.y += v1 * t1.y; a1.z += v1 * t1.z; a1.w += v1 * t1.w;
        }
        if (e < end) {
            float v0 = g_vals[e];
            int c0 = g_colidx[e];
            float4 t0 = src[c0 * 32 + lane];
            a0.x += v0 * t0.x; a0.y += v0 * t0.y; a0.z += v0 * t0.z; a0.w += v0 * t0.w;
        }
        a0.x += a1.x; a0.y += a1.y; a0.z += a1.z; a0.w += a1.w;
        ((float4*)out)[row * 32 + lane] = a0;
    }
}

// ---------------- K5: Q[side] = H^T (H @ W1_half)  [128,64] ----------------
__global__ void hyperQ_kernel(const float* __restrict__ uH, const float* __restrict__ iH,
                              const float* __restrict__ W1) {
    int side = blockIdx.x;
    const float* __restrict__ Hp = side ? iH : uH;
    const float* __restrict__ W1p = W1 + side * 128 * 64;
    __shared__ float sH[32 * 128];
    __shared__ float sRW[32 * 64];
    int tid = threadIdx.x;
    for (int t = tid; t < 32 * 128; t += 256) sH[t] = Hp[t];
    __syncthreads();
    for (int o = tid; o < 32 * 64; o += 256) {
        int r = o >> 6, j = o & 63;
        float acc = 0.f;
        for (int b = 0; b < 128; b++) acc += sH[r * 128 + b] * W1p[b * 64 + j];
        sRW[o] = acc;
    }
    __syncthreads();
    for (int o = tid; o < 128 * 64; o += 256) {
        int a = o >> 6, j = o & 63;
        float acc = 0.f;
#pragma unroll
        for (int r = 0; r < 32; r++) acc += sH[r * 128 + a] * sRW[r * 64 + j];
        g_Q[side * 128 * 64 + o] = acc;
    }
}

// ---------------- K6: AB = e3 @ Q(side)  (+b1 on user rows) ----------------
__global__ void projAB_kernel(const float* __restrict__ b1) {
    int rb = blockIdx.x * 32;
    __shared__ float sE[32 * 128];
    int tid = threadIdx.x;
    for (int t = tid; t < 32 * 128; t += 256) {
        int r = rb + (t >> 7);
        sE[t] = (r < N_) ? g_embB[r * 128 + (t & 127)] : 0.f;
    }
    __syncthreads();
    int j = tid & 63;
    int rl0 = tid >> 6;
    for (int rl = rl0; rl < 32; rl += 4) {
        int r = rb + rl;
        if (r >= N_) break;
        const float* __restrict__ Qp = (r < U_) ? g_Q : (g_Q + 128 * 64);
        float acc = (r < U_) ? b1[j] : 0.f;
#pragma unroll 8
        for (int k = 0; k < 128; k++) acc += sE[rl * 128 + k] * Qp[k * 64 + j];
        g_AB[r * 64 + j] = acc;
    }
}

// ---------------- K7: fused MLP, layer-2 via mma.sync tf32 ----------------
// block = 128 threads (4 warps), 128 rows per block.
// dyn smem: X[128][XS] tf32 bits.  static: W2 tf32 [64][WS], epilogue params.
#define XS 68
#define WS 72
#define MLP_BLOCKS ((B_ + 127) / 128)

__global__ void __launch_bounds__(128)
mlp_kernel(const int* __restrict__ uIdx, const int* __restrict__ sIdx,
           const float* __restrict__ g1, const float* __restrict__ be1,
           const float* __restrict__ W2, const float* __restrict__ b2,
           const float* __restrict__ g2, const float* __restrict__ be2,
           const float* __restrict__ W3, const float* __restrict__ b3,
           float* __restrict__ out) {
    extern __shared__ uint32_t sX[];          // [128 * XS]
    __shared__ uint32_t sW[64 * WS];          // W2 tf32, [k][n] stride WS
    __shared__ float4 sEp[64];                // (b2, g2, be2, W3) per col
    __shared__ float sg1[64], sbe1[64];

    int tid = threadIdx.x;
    // stage W2 (cvt to tf32) + params
    for (int idx = tid; idx < 64 * 64; idx += 128) {
        int k = idx >> 6, n = idx & 63;
        sW[k * WS + n] = to_tf32(W2[idx]);
    }
    if (tid < 64) {
        sg1[tid] = g1[tid]; sbe1[tid] = be1[tid];
        sEp[tid] = make_float4(b2[tid], g2[tid], be2[tid], W3[tid]);
    }

    // ---- phase 1: gather + LN1 + relu -> tf32 smem (one row per thread) ----
    {
        int r = blockIdx.x * 128 + tid;
        float x[64];
        float sum = 0.f;
        if (r < B_) {
            int u = uIdx[r], s = sIdx[r];
            const float4* __restrict__ pa = (const float4*)(g_AB + u * H_);
            const float4* __restrict__ pb = (const float4*)(g_AB + (U_ + s) * H_);
#pragma unroll
            for (int q = 0; q < 16; q++) {
                float4 a = pa[q];
                float4 b = pb[q];
                float v0 = a.x + b.x, v1 = a.y + b.y, v2 = a.z + b.z, v3 = a.w + b.w;
                x[4 * q] = v0; x[4 * q + 1] = v1; x[4 * q + 2] = v2; x[4 * q + 3] = v3;
                sum += v0 + v1 + v2 + v3;
            }
        } else {
#pragma unroll
            for (int k = 0; k < 64; k++) x[k] = 0.f;
        }
        __syncthreads();   // W2/params staged before any X store races matter
        float mu = sum * (1.f / 64.f);
        float var = 0.f;
#pragma unroll
        for (int k = 0; k < 64; k++) { float d = x[k] - mu; var += d * d; }
        float inv = rsqrtf(var * (1.f / 64.f) + EPS_);
        uint32_t* rowp = sX + tid * XS;
#pragma unroll
        for (int q = 0; q < 16; q++) {
            uint4 w;
            w.x = to_tf32(fmaxf(0.f, (x[4 * q]     - mu) * inv * sg1[4 * q]     + sbe1[4 * q]));
            w.y = to_tf32(fmaxf(0.f, (x[4 * q + 1] - mu) * inv * sg1[4 * q + 1] + sbe1[4 * q + 1]));
            w.z = to_tf32(fmaxf(0.f, (x[4 * q + 2] - mu) * inv * sg1[4 * q + 2] + sbe1[4 * q + 2]));
            w.w = to_tf32(fmaxf(0.f, (x[4 * q + 3] - mu) * inv * sg1[4 * q + 3] + sbe1[4 * q + 3]));
            *(uint4*)(rowp + 4 * q) = w;
        }
    }
    __syncthreads();

    // ---- phase 2+3: per warp, two 16-row m-tiles ----
    int wid = tid >> 5;
    int lane = tid & 31;
    int gid = lane >> 2;     // 0..7
    int tig = lane & 3;      // 0..3

#pragma unroll
    for (int mt = 0; mt < 2; mt++) {
        int mb = (wid * 2 + mt) * 16;
        const uint32_t* arow0 = sX + (mb + gid) * XS;
        const uint32_t* arow1 = sX + (mb + gid + 8) * XS;

        float c[8][4];
#pragma unroll
        for (int no = 0; no < 8; no++) {
            c[no][0] = 0.f; c[no][1] = 0.f; c[no][2] = 0.f; c[no][3] = 0.f;
        }
#pragma unroll
        for (int ko = 0; ko < 8; ko++) {
            int k0 = ko * 8;
            uint32_t a0 = arow0[k0 + tig];
            uint32_t a1 = arow1[k0 + tig];
            uint32_t a2 = arow0[k0 + tig + 4];
            uint32_t a3 = arow1[k0 + tig + 4];
            const uint32_t* bk0 = sW + (k0 + tig) * WS;
            const uint32_t* bk1 = sW + (k0 + tig + 4) * WS;
#pragma unroll
            for (int no = 0; no < 8; no++) {
                uint32_t b0 = bk0[no * 8 + gid];
                uint32_t b1 = bk1[no * 8 + gid];
                mma16n8k8(c[no], a0, a1, a2, a3, b0, b1);
            }
        }

        // epilogue: rows mb+gid and mb+gid+8; this thread owns cols no*8+2tig+{0,1}
        float ep_g2[16], ep_be2[16], ep_w3[16];
        float s0 = 0.f, q0 = 0.f, s1 = 0.f, q1 = 0.f;
#pragma unroll
        for (int no = 0; no < 8; no++) {
            int col = no * 8 + 2 * tig;
            float4 e0 = sEp[col];
            float4 e1 = sEp[col + 1];
            ep_g2[2 * no] = e0.y;  ep_be2[2 * no] = e0.z;  ep_w3[2 * no] = e0.w;
            ep_g2[2 * no + 1] = e1.y; ep_be2[2 * no + 1] = e1.z; ep_w3[2 * no + 1] = e1.w;
            c[no][0] += e0.x; c[no][1] += e1.x;   // + b2
            c[no][2] += e0.x; c[no][3] += e1.x;
            s0 += c[no][0] + c[no][1];
            q0 += c[no][0] * c[no][0] + c[no][1] * c[no][1];
            s1 += c[no][2] + c[no][3];
            q1 += c[no][2] * c[no][2] + c[no][3] * c[no][3];
        }
        s0 += __shfl_xor_sync(0xffffffffu, s0, 1);
        s0 += __shfl_xor_sync(0xffffffffu, s0, 2);
        q0 += __shfl_xor_sync(0xffffffffu, q0, 1);
        q0 += __shfl_xor_sync(0xffffffffu, q0, 2);
        s1 += __shfl_xor_sync(0xffffffffu, s1, 1);
        s1 += __shfl_xor_sync(0xffffffffu, s1, 2);
        q1 += __shfl_xor_sync(0xffffffffu, q1, 1);
        q1 += __shfl_xor_sync(0xffffffffu, q1, 2);

        float mu0 = s0 * (1.f / 64.f);
        float var0 = fmaxf(q0 * (1.f / 64.f) - mu0 * mu0, 0.f);
        float inv0 = rsqrtf(var0 + EPS_);
        float mu1 = s1 * (1.f / 64.f);
        float var1 = fmaxf(q1 * (1.f / 64.f) - mu1 * mu1, 0.f);
        float inv1 = rsqrtf(var1 + EPS_);

        float d0 = 0.f, d1 = 0.f;
#pragma unroll
        for (int no = 0; no < 8; no++) {
#pragma unroll
            for (int j = 0; j < 2; j++) {
                int p = 2 * no + j;
                float h0 = fmaxf(0.f, (c[no][j]     - mu0) * inv0 * ep_g2[p] + ep_be2[p]);
                float h1 = fmaxf(0.f, (c[no][2 + j] - mu1) * inv1 * ep_g2[p] + ep_be2[p]);
                d0 += h0 * ep_w3[p];
                d1 += h1 * ep_w3[p];
            }
        }
        d0 += __shfl_xor_sync(0xffffffffu, d0, 1);
        d0 += __shfl_xor_sync(0xffffffffu, d0, 2);
        d1 += __shfl_xor_sync(0xffffffffu, d1, 1);
        d1 += __shfl_xor_sync(0xffffffffu, d1, 2);

        if (tig == 0) {
            float bb = b3[0];
            int r0 = blockIdx.x * 128 + mb + gid;
            int r1 = r0 + 8;
            if (r0 < B_) out[r0] = d0 + bb;
            if (r1 < B_) out[r1] = d1 + bb;
        }
    }
}

// ---------------- launcher ----------------
extern "C" void kernel_launch(void* const* d_in, const int* in_sizes, int n_in,
                              void* d_out, int out_size) {
    const float* uE  = (const float*)d_in[0];
    const float* iE  = (const float*)d_in[1];
    const float* uH  = (const float*)d_in[2];
    const float* iH  = (const float*)d_in[3];
    const float* W1  = (const float*)d_in[4];
    const float* b1  = (const float*)d_in[5];
    const float* g1  = (const float*)d_in[6];
    const float* be1 = (const float*)d_in[7];
    const float* W2  = (const float*)d_in[8];
    const float* b2  = (const float*)d_in[9];
    const float* g2  = (const float*)d_in[10];
    const float* be2 = (const float*)d_in[11];
    const float* W3  = (const float*)d_in[12];
    const float* b3  = (const float*)d_in[13];
    const float* adj_vals = (const float*)d_in[14];
    const int*   adj_rows = (const int*)d_in[15];
    const int*   adj_cols = (const int*)d_in[16];
    const int*   uIdx = (const int*)d_in[17];
    const int*   sIdx = (const int*)d_in[18];
    float* out = (float*)d_out;

    static int attr_set = 0;
    if (!attr_set) {
        cudaFuncSetAttribute(mlp_kernel, cudaFuncAttributeMaxDynamicSharedMemorySize,
                             128 * XS * 4);
        attr_set = 1;
    }

    prep_kernel<<<(N_ * D_ + 255) / 256, 256>>>(uE, iE);
    hist_kernel<<<HBLKS, HTHREADS>>>(adj_rows);
    scan_kernel<<<1, 1024>>>();
    scatter_kernel<<<HBLKS, HTHREADS>>>(adj_rows, adj_cols, adj_vals);
    spmm_kernel<<<U_ + SPMM_SBLKS, 256>>>(0);   // A -> B
    spmm_kernel<<<U_ + SPMM_SBLKS, 256>>>(1);   // B -> A
    spmm_kernel<<<U_ + SPMM_SBLKS, 256>>>(0);   // A -> B  (e3 in g_embB)
    hyperQ_kernel<<<2, 256>>>(uH, iH, W1);
    projAB_kernel<<<(N_ + 31) / 32, 256>>>(b1);
    mlp_kernel<<<MLP_BLOCKS, 128, 128 * XS * 4>>>(uIdx, sIdx, g1, be1, W2, b2,
                                                  g2, be2, W3, b3, out);
}

// round 7
// speedup vs baseline: 2.8254x; 1.1593x over previous
#include <cuda_runtime.h>
#include <cuda_bf16.h>
#include <cstdint>

#define U_    339
#define S_    5825
#define N_    6164
#define D_    128
#define H_    64
#define NNZ2_ 400000
#define B_    500000
#define EPS_  1e-5f

// ---------------- device scratch (static, no allocs) ----------------
__device__ float g_embA[N_ * D_];
__device__ float g_embB[N_ * D_];
__device__ int   g_cnt[N_];          // INVARIANT: zero at call entry (zeroed by scan_kernel)
__device__ int   g_cursor[N_];
__device__ int   g_rowptr[N_ + 1];
__device__ int   g_colidx[NNZ2_];
__device__ float g_vals[NNZ2_];
__device__ float g_Q[2 * 128 * 64];   // [side][a][j]
__device__ float g_AB[N_ * H_];       // rows [0,U): A (+b1), rows [U,N): B-side

// ---------------- helpers ----------------
__device__ __forceinline__ uint32_t to_tf32(float f) {
    uint32_t r;
    asm("cvt.rna.tf32.f32 %0, %1;" : "=r"(r) : "f"(f));
    return r;
}
__device__ __forceinline__ void mma16n8k8(float c[4], uint32_t a0, uint32_t a1,
                                          uint32_t a2, uint32_t a3,
                                          uint32_t b0, uint32_t b1) {
    asm volatile(
        "mma.sync.aligned.m16n8k8.row.col.f32.tf32.tf32.f32 "
        "{%0,%1,%2,%3}, {%4,%5,%6,%7}, {%8,%9}, {%0,%1,%2,%3};"
        : "+f"(c[0]), "+f"(c[1]), "+f"(c[2]), "+f"(c[3])
        : "r"(a0), "r"(a1), "r"(a2), "r"(a3), "r"(b0), "r"(b1));
}

// ---------------- K0: fused prep (embed copy) + row histogram ----------------
#define HB2 592
#define HT2 512
#define HCH ((NNZ2_ + HB2 - 1) / HB2)   // 676
#define SQ  2
__global__ void prep_hist_kernel(const float* __restrict__ uE, const float* __restrict__ iE,
                                 const int* __restrict__ rows) {
    __shared__ int sc[N_];
    for (int t = threadIdx.x; t < N_; t += HT2) sc[t] = 0;
    __syncthreads();
    int start = blockIdx.x * HCH;
    int end = start + HCH; if (end > NNZ2_) end = NNZ2_;
    for (int i = start + threadIdx.x; i < end; i += HT2)
        atomicAdd(&sc[rows[i]], 1);
    __syncthreads();
    for (int t = threadIdx.x; t < N_; t += HT2) {
        int c = sc[t];
        if (c) atomicAdd(&g_cnt[t], c);   // g_cnt zero at entry (invariant)
    }
    // embed copy, grid-strided
    const int total = N_ * D_;
    int gsz = gridDim.x * blockDim.x;
    for (int t = blockIdx.x * blockDim.x + threadIdx.x; t < total; t += gsz)
        g_embA[t] = (t < U_ * D_) ? uE[t] : iE[t - U_ * D_];
}

// ---------------- K1: exclusive scan -> rowptr + cursor; re-zero g_cnt ----------------
#define SCAN_CH 7
__global__ void scan_kernel() {
    __shared__ int sh[1024];
    int t = threadIdx.x;
    int base = t * SCAN_CH;
    int v[SCAN_CH];
    int s = 0;
#pragma unroll
    for (int q = 0; q < SCAN_CH; q++) {
        int idx = base + q;
        int c = 0;
        if (idx < N_) { c = g_cnt[idx]; g_cnt[idx] = 0; }   // restore invariant
        v[q] = s;
        s += c;
    }
    sh[t] = s;
    __syncthreads();
    for (int off = 1; off < 1024; off <<= 1) {
        int add = (t >= off) ? sh[t - off] : 0;
        __syncthreads();
        sh[t] += add;
        __syncthreads();
    }
    int excl = (t == 0) ? 0 : sh[t - 1];
#pragma unroll
    for (int q = 0; q < SCAN_CH; q++) {
        int idx = base + q;
        if (idx < N_) {
            int p = excl + v[q];
            g_rowptr[idx] = p;
            g_cursor[idx] = p;
        }
    }
    if (t == 0) g_rowptr[N_] = NNZ2_;
}

// ---------------- K2: scatter into CSR (block-local positions + per-row reservation) ----------------
__global__ void scatter_kernel(const int* __restrict__ rows, const int* __restrict__ cols,
                               const float* __restrict__ vals) {
    __shared__ int sc[N_];
    for (int t = threadIdx.x; t < N_; t += HT2) sc[t] = 0;
    __syncthreads();
    int start = blockIdx.x * HCH;
    int end = start + HCH; if (end > NNZ2_) end = NNZ2_;

    int myrow[SQ], mycol[SQ], mypos[SQ];
    float myval[SQ];
#pragma unroll
    for (int q = 0; q < SQ; q++) {
        int i = start + q * HT2 + threadIdx.x;
        bool valid = (i < end);
        int r = valid ? rows[i] : 0;
        myrow[q] = valid ? r : -1;
        mycol[q] = valid ? cols[i] : 0;
        myval[q] = valid ? vals[i] : 0.f;
        mypos[q] = valid ? atomicAdd(&sc[r], 1) : 0;
    }
    __syncthreads();
    for (int t = threadIdx.x; t < N_; t += HT2) {
        int c = sc[t];
        if (c) sc[t] = atomicAdd(&g_cursor[t], c);
    }
    __syncthreads();
#pragma unroll
    for (int q = 0; q < SQ; q++) {
        if (myrow[q] >= 0) {
            int p = sc[myrow[q]] + mypos[q];
            g_colidx[p] = mycol[q];
            g_vals[p] = myval[q];
        }
    }
}

// ---------------- K3: CSR SpMM, load-balanced ----------------
#define SPMM_SBLKS ((S_ + 7) / 8)
__global__ void spmm_kernel(int dir) {
    const float* __restrict__ in = dir ? g_embB : g_embA;
    float* __restrict__ out = dir ? g_embA : g_embB;
    const float4* __restrict__ src = (const float4*)in;
    int lane = threadIdx.x & 31;
    int w = threadIdx.x >> 5;

    if (blockIdx.x < U_) {
        int row = blockIdx.x;
        int beg = g_rowptr[row], end = g_rowptr[row + 1];
        float4 a = {0.f, 0.f, 0.f, 0.f};
        float4 a1 = {0.f, 0.f, 0.f, 0.f};
        int e = beg + w;
        for (; e + 8 < end; e += 16) {
            float v0 = g_vals[e];     int c0 = g_colidx[e];
            float v1 = g_vals[e + 8]; int c1 = g_colidx[e + 8];
            float4 t0 = src[c0 * 32 + lane];
            float4 t1 = src[c1 * 32 + lane];
            a.x += v0 * t0.x;  a.y += v0 * t0.y;  a.z += v0 * t0.z;  a.w += v0 * t0.w;
            a1.x += v1 * t1.x; a1.y += v1 * t1.y; a1.z += v1 * t1.z; a1.w += v1 * t1.w;
        }
        if (e < end) {
            float v = g_vals[e];
            int c = g_colidx[e];
            float4 t = src[c * 32 + lane];
            a.x += v * t.x; a.y += v * t.y; a.z += v * t.z; a.w += v * t.w;
        }
        a.x += a1.x; a.y += a1.y; a.z += a1.z; a.w += a1.w;
        __shared__ float4 red[256];
        int tid = threadIdx.x;
        red[tid] = a; __syncthreads();
        if (tid < 128) {
            float4 b = red[tid + 128];
            a.x += b.x; a.y += b.y; a.z += b.z; a.w += b.w;
            red[tid] = a;
        }
        __syncthreads();
        if (tid < 64) {
            float4 b = red[tid + 64];
            a.x += b.x; a.y += b.y; a.z += b.z; a.w += b.w;
            red[tid] = a;
        }
        __syncthreads();
        if (tid < 32) {
            float4 b = red[tid + 32];
            a.x += b.x; a.y += b.y; a.z += b.z; a.w += b.w;
            ((float4*)out)[row * 32 + lane] = a;
        }
    } else {
        int row = U_ + (blockIdx.x - U_) * 8 + w;
        if (row >= N_) return;
        int beg = g_rowptr[row], end = g_rowptr[row + 1];
        float4 a0 = {0.f, 0.f, 0.f, 0.f};
        float4 a1 = {0.f, 0.f, 0.f, 0.f};
        float4 a2 = {0.f, 0.f, 0.f, 0.f};
        float4 a3 = {0.f, 0.f, 0.f, 0.f};
        int e = beg;
        for (; e + 4 <= end; e += 4) {
            float v0 = g_vals[e],     v1 = g_vals[e + 1];
            float v2 = g_vals[e + 2], v3 = g_vals[e + 3];
            int c0 = g_colidx[e],     c1 = g_colidx[e + 1];
            int c2 = g_colidx[e + 2], c3 = g_colidx[e + 3];
            float4 t0 = src[c0 * 32 + lane];
            float4 t1 = src[c1 * 32 + lane];
            float4 t2 = src[c2 * 32 + lane];
            float4 t3 = src[c3 * 32 + lane];
            a0.x += v0 * t0.x; a0.y += v0 * t0.y; a0.z += v0 * t0.z; a0.w += v0 * t0.w;
            a1.x += v1 * t1.x; a1.y += v1 * t1.y; a1.z += v1 * t1.z; a1.w += v1 * t1.w;
            a2.x += v2 * t2.x; a2.y += v2 * t2.y; a2.z += v2 * t2.z; a2.w += v2 * t2.w;
            a3.x += v3 * t3.x; a3.y += v3 * t3.y; a3.z += v3 * t3.z; a3.w += v3 * t3.w;
        }
        for (; e < end; e++) {
            float v0 = g_vals[e];
            int c0 = g_colidx[e];
            float4 t0 = src[c0 * 32 + lane];
            a0.x += v0 * t0.x; a0.y += v0 * t0.y; a0.z += v0 * t0.z; a0.w += v0 * t0.w;
        }
        a0.x += a1.x + a2.x + a3.x;
        a0.y += a1.y + a2.y + a3.y;
        a0.z += a1.z + a2.z + a3.z;
        a0.w += a1.w + a2.w + a3.w;
        ((float4*)out)[row * 32 + lane] = a0;
    }
}

// ---------------- K4: Q[side] = H^T (H @ W1_half)  [128,64] ----------------
__global__ void hyperQ_kernel(const float* __restrict__ uH, const float* __restrict__ iH,
                              const float* __restrict__ W1) {
    int side = blockIdx.x;
    const float* __restrict__ Hp = side ? iH : uH;
    const float* __restrict__ W1p = W1 + side * 128 * 64;
    __shared__ float sH[32 * 128];
    __shared__ float sRW[32 * 64];
    int tid = threadIdx.x;
    for (int t = tid; t < 32 * 128; t += 256) sH[t] = Hp[t];
    __syncthreads();
    for (int o = tid; o < 32 * 64; o += 256) {
        int r = o >> 6, j = o & 63;
        float acc = 0.f;
        for (int b = 0; b < 128; b++) acc += sH[r * 128 + b] * W1p[b * 64 + j];
        sRW[o] = acc;
    }
    __syncthreads();
    for (int o = tid; o < 128 * 64; o += 256) {
        int a = o >> 6, j = o & 63;
        float acc = 0.f;
#pragma unroll
        for (int r = 0; r < 32; r++) acc += sH[r * 128 + a] * sRW[r * 64 + j];
        g_Q[side * 128 * 64 + o] = acc;
    }
}

// ---------------- K5: AB = e3 @ Q(side)  (+b1 on user rows) ----------------
__global__ void projAB_kernel(const float* __restrict__ b1) {
    int rb = blockIdx.x * 32;
    __shared__ float sE[32 * 128];
    int tid = threadIdx.x;
    for (int t = tid; t < 32 * 128; t += 256) {
        int r = rb + (t >> 7);
        sE[t] = (r < N_) ? g_embB[r * 128 + (t & 127)] : 0.f;
    }
    __syncthreads();
    int j = tid & 63;
    int rl0 = tid >> 6;
    for (int rl = rl0; rl < 32; rl += 4) {
        int r = rb + rl;
        if (r >= N_) break;
        const float* __restrict__ Qp = (r < U_) ? g_Q : (g_Q + 128 * 64);
        float acc = (r < U_) ? b1[j] : 0.f;
#pragma unroll 8
        for (int k = 0; k < 128; k++) acc += sE[rl * 128 + k] * Qp[k * 64 + j];
        g_AB[r * 64 + j] = acc;
    }
}

// ---------------- K6: persistent fused MLP, layer-2 via mma.sync tf32 ----------------
// 592 blocks x 128 threads; W2 staged once per block; warp-local tiles (no block syncs in loop).
#define XS 68
#define WS 72
#define NT_ ((B_ + 127) / 128)
#define MLP_GRID 592

__global__ void __launch_bounds__(128)
mlp_kernel(const int* __restrict__ uIdx, const int* __restrict__ sIdx,
           const float* __restrict__ g1, const float* __restrict__ be1,
           const float* __restrict__ W2, const float* __restrict__ b2,
           const float* __restrict__ g2, const float* __restrict__ be2,
           const float* __restrict__ W3, const float* __restrict__ b3,
           float* __restrict__ out) {
    extern __shared__ uint32_t sX[];          // [128 * XS]
    __shared__ uint32_t sW[64 * WS];          // W2 tf32, [k][n] stride WS
    __shared__ float4 sEp[64];                // (b2, g2, be2, W3) per col
    __shared__ float sg1[64], sbe1[64];

    int tid = threadIdx.x;
    for (int idx = tid; idx < 64 * 64; idx += 128) {
        int k = idx >> 6, n = idx & 63;
        sW[k * WS + n] = to_tf32(W2[idx]);
    }
    if (tid < 64) {
        sg1[tid] = g1[tid]; sbe1[tid] = be1[tid];
        sEp[tid] = make_float4(b2[tid], g2[tid], be2[tid], W3[tid]);
    }
    __syncthreads();
    float bb = b3[0];

    int wid = tid >> 5;
    int lane = tid & 31;
    int gid = lane >> 2;     // 0..7
    int tig = lane & 3;      // 0..3
    uint32_t* rowp = sX + tid * XS;

    for (int tile = blockIdx.x; tile < NT_; tile += MLP_GRID) {
        int r = tile * 128 + tid;

        // ---- phase 1: gather + LN1 + relu -> tf32 smem (row tid) ----
        {
            float x[64];
            float sum = 0.f;
            if (r < B_) {
                int u = uIdx[r], s = sIdx[r];
                const float4* __restrict__ pa = (const float4*)(g_AB + u * H_);
                const float4* __restrict__ pb = (const float4*)(g_AB + (U_ + s) * H_);
#pragma unroll
                for (int q = 0; q < 16; q++) {
                    float4 a = pa[q];
                    float4 b = pb[q];
                    float v0 = a.x + b.x, v1 = a.y + b.y, v2 = a.z + b.z, v3 = a.w + b.w;
                    x[4 * q] = v0; x[4 * q + 1] = v1; x[4 * q + 2] = v2; x[4 * q + 3] = v3;
                    sum += v0 + v1 + v2 + v3;
                }
            } else {
#pragma unroll
                for (int k = 0; k < 64; k++) x[k] = 0.f;
            }
            float mu = sum * (1.f / 64.f);
            float var = 0.f;
#pragma unroll
            for (int k = 0; k < 64; k++) { float d = x[k] - mu; var += d * d; }
            float inv = rsqrtf(var * (1.f / 64.f) + EPS_);
#pragma unroll
            for (int q = 0; q < 16; q++) {
                uint4 w;
                w.x = to_tf32(fmaxf(0.f, (x[4 * q]     - mu) * inv * sg1[4 * q]     + sbe1[4 * q]));
                w.y = to_tf32(fmaxf(0.f, (x[4 * q + 1] - mu) * inv * sg1[4 * q + 1] + sbe1[4 * q + 1]));
                w.z = to_tf32(fmaxf(0.f, (x[4 * q + 2] - mu) * inv * sg1[4 * q + 2] + sbe1[4 * q + 2]));
                w.w = to_tf32(fmaxf(0.f, (x[4 * q + 3] - mu) * inv * sg1[4 * q + 3] + sbe1[4 * q + 3]));
                *(uint4*)(rowp + 4 * q) = w;
            }
        }
        __syncwarp();   // warp w reads only rows [32w,32w+32) == rows its threads wrote

        // ---- phase 2+3: per warp, two 16-row m-tiles ----
#pragma unroll
        for (int mt = 0; mt < 2; mt++) {
            int mb = (wid * 2 + mt) * 16;
            const uint32_t* arow0 = sX + (mb + gid) * XS;
            const uint32_t* arow1 = sX + (mb + gid + 8) * XS;

            float c[8][4];
#pragma unroll
            for (int no = 0; no < 8; no++) {
                c[no][0] = 0.f; c[no][1] = 0.f; c[no][2] = 0.f; c[no][3] = 0.f;
            }
#pragma unroll
            for (int ko = 0; ko < 8; ko++) {
                int k0 = ko * 8;
                uint32_t a0 = arow0[k0 + tig];
                uint32_t a1 = arow1[k0 + tig];
                uint32_t a2 = arow0[k0 + tig + 4];
                uint32_t a3 = arow1[k0 + tig + 4];
                const uint32_t* bk0 = sW + (k0 + tig) * WS;
                const uint32_t* bk1 = sW + (k0 + tig + 4) * WS;
#pragma unroll
                for (int no = 0; no < 8; no++) {
                    uint32_t b0 = bk0[no * 8 + gid];
                    uint32_t b1 = bk1[no * 8 + gid];
                    mma16n8k8(c[no], a0, a1, a2, a3, b0, b1);
                }
            }

            float ep_g2[16], ep_be2[16], ep_w3[16];
            float s0 = 0.f, q0 = 0.f, s1 = 0.f, q1 = 0.f;
#pragma unroll
            for (int no = 0; no < 8; no++) {
                int col = no * 8 + 2 * tig;
                float4 e0 = sEp[col];
                float4 e1 = sEp[col + 1];
                ep_g2[2 * no] = e0.y;  ep_be2[2 * no] = e0.z;  ep_w3[2 * no] = e0.w;
                ep_g2[2 * no + 1] = e1.y; ep_be2[2 * no + 1] = e1.z; ep_w3[2 * no + 1] = e1.w;
                c[no][0] += e0.x; c[no][1] += e1.x;
                c[no][2] += e0.x; c[no][3] += e1.x;
                s0 += c[no][0] + c[no][1];
                q0 += c[no][0] * c[no][0] + c[no][1] * c[no][1];
                s1 += c[no][2] + c[no][3];
                q1 += c[no][2] * c[no][2] + c[no][3] * c[no][3];
            }
            s0 += __shfl_xor_sync(0xffffffffu, s0, 1);
            s0 += __shfl_xor_sync(0xffffffffu, s0, 2);
            q0 += __shfl_xor_sync(0xffffffffu, q0, 1);
            q0 += __shfl_xor_sync(0xffffffffu, q0, 2);
            s1 += __shfl_xor_sync(0xffffffffu, s1, 1);
            s1 += __shfl_xor_sync(0xffffffffu, s1, 2);
            q1 += __shfl_xor_sync(0xffffffffu, q1, 1);
            q1 += __shfl_xor_sync(0xffffffffu, q1, 2);

            float mu0 = s0 * (1.f / 64.f);
            float var0 = fmaxf(q0 * (1.f / 64.f) - mu0 * mu0, 0.f);
            float inv0 = rsqrtf(var0 + EPS_);
            float mu1 = s1 * (1.f / 64.f);
            float var1 = fmaxf(q1 * (1.f / 64.f) - mu1 * mu1, 0.f);
            float inv1 = rsqrtf(var1 + EPS_);

            float d0 = 0.f, d1 = 0.f;
#pragma unroll
            for (int no = 0; no < 8; no++) {
#pragma unroll
                for (int j = 0; j < 2; j++) {
                    int p = 2 * no + j;
                    float h0 = fmaxf(0.f, (c[no][j]     - mu0) * inv0 * ep_g2[p] + ep_be2[p]);
                    float h1 = fmaxf(0.f, (c[no][2 + j] - mu1) * inv1 * ep_g2[p] + ep_be2[p]);
                    d0 += h0 * ep_w3[p];
                    d1 += h1 * ep_w3[p];
                }
            }
            d0 += __shfl_xor_sync(0xffffffffu, d0, 1);
            d0 += __shfl_xor_sync(0xffffffffu, d0, 2);
            d1 += __shfl_xor_sync(0xffffffffu, d1, 1);
            d1 += __shfl_xor_sync(0xffffffffu, d1, 2);

            if (tig == 0) {
                int r0 = tile * 128 + mb + gid;
                int r1 = r0 + 8;
                if (r0 < B_) out[r0] = d0 + bb;
                if (r1 < B_) out[r1] = d1 + bb;
            }
        }
        __syncwarp();   // all reads of sX done before next iteration overwrites
    }
}

// ---------------- launcher ----------------
extern "C" void kernel_launch(void* const* d_in, const int* in_sizes, int n_in,
                              void* d_out, int out_size) {
    const float* uE  = (const float*)d_in[0];
    const float* iE  = (const float*)d_in[1];
    const float* uH  = (const float*)d_in[2];
    const float* iH  = (const float*)d_in[3];
    const float* W1  = (const float*)d_in[4];
    const float* b1  = (const float*)d_in[5];
    const float* g1  = (const float*)d_in[6];
    const float* be1 = (const float*)d_in[7];
    const float* W2  = (const float*)d_in[8];
    const float* b2  = (const float*)d_in[9];
    const float* g2  = (const float*)d_in[10];
    const float* be2 = (const float*)d_in[11];
    const float* W3  = (const float*)d_in[12];
    const float* b3  = (const float*)d_in[13];
    const float* adj_vals = (const float*)d_in[14];
    const int*   adj_rows = (const int*)d_in[15];
    const int*   adj_cols = (const int*)d_in[16];
    const int*   uIdx = (const int*)d_in[17];
    const int*   sIdx = (const int*)d_in[18];
    float* out = (float*)d_out;

    static int attr_set = 0;
    if (!attr_set) {
        cudaFuncSetAttribute(mlp_kernel, cudaFuncAttributeMaxDynamicSharedMemorySize,
                             128 * XS * 4);
        attr_set = 1;
    }

    prep_hist_kernel<<<HB2, HT2>>>(uE, iE, adj_rows);
    scan_kernel<<<1, 1024>>>();
    scatter_kernel<<<HB2, HT2>>>(adj_rows, adj_cols, adj_vals);
    spmm_kernel<<<U_ + SPMM_SBLKS, 256>>>(0);   // A -> B
    spmm_kernel<<<U_ + SPMM_SBLKS, 256>>>(1);   // B -> A
    spmm_kernel<<<U_ + SPMM_SBLKS, 256>>>(0);   // A -> B  (e3 in g_embB)
    hyperQ_kernel<<<2, 256>>>(uH, iH, W1);
    projAB_kernel<<<(N_ + 31) / 32, 256>>>(b1);
    mlp_kernel<<<MLP_GRID, 128, 128 * XS * 4>>>(uIdx, sIdx, g1, be1, W2, b2,
                                                g2, be2, W3, b3, out);
}

// round 9
// speedup vs baseline: 3.1011x; 1.0976x over previous
#include <cuda_runtime.h>
#include <cuda_bf16.h>
#include <cstdint>

#define U_    339
#define S_    5825
#define N_    6164
#define D_    128
#define H_    64
#define NNZ2_ 400000
#define B_    500000
#define EPS_  1e-5f

// ---------------- device scratch (static, no allocs) ----------------
__device__ float g_embA[N_ * D_];
__device__ float g_embB[N_ * D_];
__device__ int   g_cnt[N_];          // INVARIANT: zero at call entry (zeroed by scan)
__device__ int   g_cursor[N_];
__device__ int   g_rowptr[N_ + 1];
__device__ int   g_colidx[NNZ2_];
__device__ float g_vals[NNZ2_];
__device__ float g_Q[2 * 128 * 64];  // side0 = Qu (uH,W1top), side1 = Qi (iH,W1bot)
__device__ float g_P[N_ * H_];       // P[r] = e2[r] @ Q_swapped
__device__ float g_AB[N_ * H_];      // rows [0,U): +b1

// ---------------- helpers ----------------
__device__ __forceinline__ uint32_t to_tf32(float f) {
    uint32_t r;
    asm("cvt.rna.tf32.f32 %0, %1;" : "=r"(r) : "f"(f));
    return r;
}
__device__ __forceinline__ void mma16n8k8(float c[4], uint32_t a0, uint32_t a1,
                                          uint32_t a2, uint32_t a3,
                                          uint32_t b0, uint32_t b1) {
    asm volatile(
        "mma.sync.aligned.m16n8k8.row.col.f32.tf32.tf32.f32 "
        "{%0,%1,%2,%3}, {%4,%5,%6,%7}, {%8,%9}, {%0,%1,%2,%3};"
        : "+f"(c[0]), "+f"(c[1]), "+f"(c[2]), "+f"(c[3])
        : "r"(a0), "r"(a1), "r"(a2), "r"(a3), "r"(b0), "r"(b1));
}

// ---------------- K0: fused prep (embed copy) + row histogram ----------------
#define HB2 592
#define HT2 512
#define HCH ((NNZ2_ + HB2 - 1) / HB2)   // 676
#define SQ  2
__global__ void prep_hist_kernel(const float* __restrict__ uE, const float* __restrict__ iE,
                                 const int* __restrict__ rows) {
    __shared__ int sc[N_];
    for (int t = threadIdx.x; t < N_; t += HT2) sc[t] = 0;
    __syncthreads();
    int start = blockIdx.x * HCH;
    int end = start + HCH; if (end > NNZ2_) end = NNZ2_;
    for (int i = start + threadIdx.x; i < end; i += HT2)
        atomicAdd(&sc[rows[i]], 1);
    __syncthreads();
    for (int t = threadIdx.x; t < N_; t += HT2) {
        int c = sc[t];
        if (c) atomicAdd(&g_cnt[t], c);
    }
    const int total = N_ * D_;
    int gsz = gridDim.x * blockDim.x;
    for (int t = blockIdx.x * blockDim.x + threadIdx.x; t < total; t += gsz)
        g_embA[t] = (t < U_ * D_) ? uE[t] : iE[t - U_ * D_];
}

// ---------------- K1: block0 = scan -> rowptr/cursor (+re-zero cnt); blocks1,2 = hyperQ ----------------
#define SCAN_CH 7
__global__ void scan_hyperQ_kernel(const float* __restrict__ uH, const float* __restrict__ iH,
                                   const float* __restrict__ W1) {
    int t = threadIdx.x;
    if (blockIdx.x == 0) {
        __shared__ int sh[1024];
        int base = t * SCAN_CH;
        int v[SCAN_CH];
        int s = 0;
#pragma unroll
        for (int q = 0; q < SCAN_CH; q++) {
            int idx = base + q;
            int c = 0;
            if (idx < N_) { c = g_cnt[idx]; g_cnt[idx] = 0; }
            v[q] = s;
            s += c;
        }
        sh[t] = s;
        __syncthreads();
        for (int off = 1; off < 1024; off <<= 1) {
            int add = (t >= off) ? sh[t - off] : 0;
            __syncthreads();
            sh[t] += add;
            __syncthreads();
        }
        int excl = (t == 0) ? 0 : sh[t - 1];
#pragma unroll
        for (int q = 0; q < SCAN_CH; q++) {
            int idx = base + q;
            if (idx < N_) {
                int p = excl + v[q];
                g_rowptr[idx] = p;
                g_cursor[idx] = p;
            }
        }
        if (t == 0) g_rowptr[N_] = NNZ2_;
    } else {
        int side = blockIdx.x - 1;
        const float* __restrict__ Hp = side ? iH : uH;
        const float* __restrict__ W1p = W1 + side * 128 * 64;
        __shared__ float sH[32 * 128];
        __shared__ float sRW[32 * 64];
        for (int i = t; i < 32 * 128; i += 1024) sH[i] = Hp[i];
        __syncthreads();
        for (int o = t; o < 32 * 64; o += 1024) {
            int r = o >> 6, j = o & 63;
            float acc = 0.f;
            for (int b = 0; b < 128; b++) acc += sH[r * 128 + b] * W1p[b * 64 + j];
            sRW[o] = acc;
        }
        __syncthreads();
        for (int o = t; o < 128 * 64; o += 1024) {
            int a = o >> 6, j = o & 63;
            float acc = 0.f;
#pragma unroll
            for (int r = 0; r < 32; r++) acc += sH[r * 128 + a] * sRW[r * 64 + j];
            g_Q[side * 128 * 64 + o] = acc;
        }
    }
}

// ---------------- K2: scatter into CSR ----------------
__global__ void scatter_kernel(const int* __restrict__ rows, const int* __restrict__ cols,
                               const float* __restrict__ vals) {
    __shared__ int sc[N_];
    for (int t = threadIdx.x; t < N_; t += HT2) sc[t] = 0;
    __syncthreads();
    int start = blockIdx.x * HCH;
    int end = start + HCH; if (end > NNZ2_) end = NNZ2_;

    int myrow[SQ], mycol[SQ], mypos[SQ];
    float myval[SQ];
#pragma unroll
    for (int q = 0; q < SQ; q++) {
        int i = start + q * HT2 + threadIdx.x;
        bool valid = (i < end);
        int r = valid ? rows[i] : 0;
        myrow[q] = valid ? r : -1;
        mycol[q] = valid ? cols[i] : 0;
        myval[q] = valid ? vals[i] : 0.f;
        mypos[q] = valid ? atomicAdd(&sc[r], 1) : 0;
    }
    __syncthreads();
    for (int t = threadIdx.x; t < N_; t += HT2) {
        int c = sc[t];
        if (c) sc[t] = atomicAdd(&g_cursor[t], c);
    }
    __syncthreads();
#pragma unroll
    for (int q = 0; q < SQ; q++) {
        if (myrow[q] >= 0) {
            int p = sc[myrow[q]] + mypos[q];
            g_colidx[p] = mycol[q];
            g_vals[p] = myval[q];
        }
    }
}

// ---------------- K3: CSR SpMM 128-wide, load-balanced ----------------
#define SPMM_SBLKS ((S_ + 7) / 8)
__global__ void spmm_kernel(int dir) {
    const float* __restrict__ in = dir ? g_embB : g_embA;
    float* __restrict__ out = dir ? g_embA : g_embB;
    const float4* __restrict__ src = (const float4*)in;
    int lane = threadIdx.x & 31;
    int w = threadIdx.x >> 5;

    if (blockIdx.x < U_) {
        int row = blockIdx.x;
        int beg = g_rowptr[row], end = g_rowptr[row + 1];
        float4 a = {0.f, 0.f, 0.f, 0.f};
        float4 a1 = {0.f, 0.f, 0.f, 0.f};
        int e = beg + w;
        for (; e + 8 < end; e += 16) {
            float v0 = g_vals[e];     int c0 = g_colidx[e];
            float v1 = g_vals[e + 8]; int c1 = g_colidx[e + 8];
            float4 t0 = src[c0 * 32 + lane];
            float4 t1 = src[c1 * 32 + lane];
            a.x += v0 * t0.x;  a.y += v0 * t0.y;  a.z += v0 * t0.z;  a.w += v0 * t0.w;
            a1.x += v1 * t1.x; a1.y += v1 * t1.y; a1.z += v1 * t1.z; a1.w += v1 * t1.w;
        }
        if (e < end) {
            float v = g_vals[e];
            int c = g_colidx[e];
            float4 t = src[c * 32 + lane];
            a.x += v * t.x; a.y += v * t.y; a.z += v * t.z; a.w += v * t.w;
        }
        a.x += a1.x; a.y += a1.y; a.z += a1.z; a.w += a1.w;
        __shared__ float4 red[256];
        int tid = threadIdx.x;
        red[tid] = a; __syncthreads();
        if (tid < 128) {
            float4 b = red[tid + 128];
            a.x += b.x; a.y += b.y; a.z += b.z; a.w += b.w;
            red[tid] = a;
        }
        __syncthreads();
        if (tid < 64) {
            float4 b = red[tid + 64];
            a.x += b.x; a.y += b.y; a.z += b.z; a.w += b.w;
            red[tid] = a;
        }
        __syncthreads();
        if (tid < 32) {
            float4 b = red[tid + 32];
            a.x += b.x; a.y += b.y; a.z += b.z; a.w += b.w;
            ((float4*)out)[row * 32 + lane] = a;
        }
    } else {
        int row = U_ + (blockIdx.x - U_) * 8 + w;
        if (row >= N_) return;
        int beg = g_rowptr[row], end = g_rowptr[row + 1];
        float4 a0 = {0.f, 0.f, 0.f, 0.f};
        float4 a1 = {0.f, 0.f, 0.f, 0.f};
        float4 a2 = {0.f, 0.f, 0.f, 0.f};
        float4 a3 = {0.f, 0.f, 0.f, 0.f};
        int e = beg;
        for (; e + 4 <= end; e += 4) {
            float v0 = g_vals[e],     v1 = g_vals[e + 1];
            float v2 = g_vals[e + 2], v3 = g_vals[e + 3];
            int c0 = g_colidx[e],     c1 = g_colidx[e + 1];
            int c2 = g_colidx[e + 2], c3 = g_colidx[e + 3];
            float4 t0 = src[c0 * 32 + lane];
            float4 t1 = src[c1 * 32 + lane];
            float4 t2 = src[c2 * 32 + lane];
            float4 t3 = src[c3 * 32 + lane];
            a0.x += v0 * t0.x; a0.y += v0 * t0.y; a0.z += v0 * t0.z; a0.w += v0 * t0.w;
            a1.x += v1 * t1.x; a1.y += v1 * t1.y; a1.z += v1 * t1.z; a1.w += v1 * t1.w;
            a2.x += v2 * t2.x; a2.y += v2 * t2.y; a2.z += v2 * t2.z; a2.w += v2 * t2.w;
            a3.x += v3 * t3.x; a3.y += v3 * t3.y; a3.z += v3 * t3.z; a3.w += v3 * t3.w;
        }
        for (; e < end; e++) {
            float v0 = g_vals[e];
            int c0 = g_colidx[e];
            float4 t0 = src[c0 * 32 + lane];
            a0.x += v0 * t0.x; a0.y += v0 * t0.y; a0.z += v0 * t0.z; a0.w += v0 * t0.w;
        }
        a0.x += a1.x + a2.x + a3.x;
        a0.y += a1.y + a2.y + a3.y;
        a0.z += a1.z + a2.z + a3.z;
        a0.w += a1.w + a2.w + a3.w;
        ((float4*)out)[row * 32 + lane] = a0;
    }
}

// ---------------- K4: P = e2 @ Q_swapped  (e2 in g_embA) ----------------
// u-rows project with Qi (side1), s-rows with Qu (side0):
// AB[u] = sum_s A[u,s] (e2[s]@Qu)  -> P[s] uses Qu;  AB[s] = sum_u A[s,u] (e2[u]@Qi) -> P[u] uses Qi.
__global__ void projP_kernel() {
    int rb = blockIdx.x * 32;
    __shared__ float sE[32 * 128];
    int tid = threadIdx.x;
    for (int t = tid; t < 32 * 128; t += 256) {
        int r = rb + (t >> 7);
        sE[t] = (r < N_) ? g_embA[r * 128 + (t & 127)] : 0.f;
    }
    __syncthreads();
    int j = tid & 63;
    int rl0 = tid >> 6;
    for (int rl = rl0; rl < 32; rl += 4) {
        int r = rb + rl;
        if (r >= N_) break;
        const float* __restrict__ Qp = (r < U_) ? (g_Q + 128 * 64) : g_Q;  // swapped
        float acc = 0.f;
#pragma unroll 8
        for (int k = 0; k < 128; k++) acc += sE[rl * 128 + k] * Qp[k * 64 + j];
        g_P[r * 64 + j] = acc;
    }
}

// ---------------- K5: 64-wide SpMM: AB = A @ P (+b1 on u-rows) ----------------
__global__ void spmm64_kernel(const float* __restrict__ b1) {
    const float2* __restrict__ src = (const float2*)g_P;
    int lane = threadIdx.x & 31;
    int w = threadIdx.x >> 5;

    if (blockIdx.x < U_) {
        int row = blockIdx.x;
        int beg = g_rowptr[row], end = g_rowptr[row + 1];
        float2 a = {0.f, 0.f};
        float2 a1 = {0.f, 0.f};
        int e = beg + w;
        for (; e + 8 < end; e += 16) {
            float v0 = g_vals[e];     int c0 = g_colidx[e];
            float v1 = g_vals[e + 8]; int c1 = g_colidx[e + 8];
            float2 t0 = src[c0 * 32 + lane];
            float2 t1 = src[c1 * 32 + lane];
            a.x += v0 * t0.x;  a.y += v0 * t0.y;
            a1.x += v1 * t1.x; a1.y += v1 * t1.y;
        }
        if (e < end) {
            float v = g_vals[e];
            int c = g_colidx[e];
            float2 t = src[c * 32 + lane];
            a.x += v * t.x; a.y += v * t.y;
        }
        a.x += a1.x; a.y += a1.y;
        __shared__ float2 red[256];
        int tid = threadIdx.x;
        red[tid] = a; __syncthreads();
        if (tid < 128) {
            float2 b = red[tid + 128];
            a.x += b.x; a.y += b.y;
            red[tid] = a;
        }
        __syncthreads();
        if (tid < 64) {
            float2 b = red[tid + 64];
            a.x += b.x; a.y += b.y;
            red[tid] = a;
        }
        __syncthreads();
        if (tid < 32) {
            float2 b = red[tid + 32];
            a.x += b.x; a.y += b.y;
            a.x += b1[2 * lane];
            a.y += b1[2 * lane + 1];
            ((float2*)g_AB)[row * 32 + lane] = a;
        }
    } else {
        int row = U_ + (blockIdx.x - U_) * 8 + w;
        if (row >= N_) return;
        int beg = g_rowptr[row], end = g_rowptr[row + 1];
        float2 a0 = {0.f, 0.f};
        float2 a1 = {0.f, 0.f};
        float2 a2 = {0.f, 0.f};
        float2 a3 = {0.f, 0.f};
        int e = beg;
        for (; e + 4 <= end; e += 4) {
            float v0 = g_vals[e],     v1 = g_vals[e + 1];
            float v2 = g_vals[e + 2], v3 = g_vals[e + 3];
            int c0 = g_colidx[e],     c1 = g_colidx[e + 1];
            int c2 = g_colidx[e + 2], c3 = g_colidx[e + 3];
            float2 t0 = src[c0 * 32 + lane];
            float2 t1 = src[c1 * 32 + lane];
            float2 t2 = src[c2 * 32 + lane];
            float2 t3 = src[c3 * 32 + lane];
            a0.x += v0 * t0.x; a0.y += v0 * t0.y;
            a1.x += v1 * t1.x; a1.y += v1 * t1.y;
            a2.x += v2 * t2.x; a2.y += v2 * t2.y;
            a3.x += v3 * t3.x; a3.y += v3 * t3.y;
        }
        for (; e < end; e++) {
            float v0 = g_vals[e];
            int c0 = g_colidx[e];
            float2 t0 = src[c0 * 32 + lane];
            a0.x += v0 * t0.x; a0.y += v0 * t0.y;
        }
        a0.x += a1.x + a2.x + a3.x;
        a0.y += a1.y + a2.y + a3.y;
        ((float2*)g_AB)[row * 32 + lane] = a0;
    }
}

// ---------------- K6: persistent fused MLP, layer-2 via mma.sync tf32 ----------------
#define XS 68
#define WS 72
#define NT_ ((B_ + 127) / 128)
#define MLP_GRID 592

__global__ void __launch_bounds__(128)
mlp_kernel(const int* __restrict__ uIdx, const int* __restrict__ sIdx,
           const float* __restrict__ g1, const float* __restrict__ be1,
           const float* __restrict__ W2, const float* __restrict__ b2,
           const float* __restrict__ g2, const float* __restrict__ be2,
           const float* __restrict__ W3, const float* __restrict__ b3,
           float* __restrict__ out) {
    extern __shared__ uint32_t sX[];          // [128 * XS]
    __shared__ uint32_t sW[64 * WS];
    __shared__ float4 sEp[64];
    __shared__ float sg1[64], sbe1[64];

    int tid = threadIdx.x;
    for (int idx = tid; idx < 64 * 64; idx += 128) {
        int k = idx >> 6, n = idx & 63;
        sW[k * WS + n] = to_tf32(W2[idx]);
    }
    if (tid < 64) {
        sg1[tid] = g1[tid]; sbe1[tid] = be1[tid];
        sEp[tid] = make_float4(b2[tid], g2[tid], be2[tid], W3[tid]);
    }
    __syncthreads();
    float bb = b3[0];

    int wid = tid >> 5;
    int lane = tid & 31;
    int gid = lane >> 2;
    int tig = lane & 3;
    uint32_t* rowp = sX + tid * XS;

    for (int tile = blockIdx.x; tile < NT_; tile += MLP_GRID) {
        int r = tile * 128 + tid;

        {
            float x[64];
            float sum = 0.f;
            if (r < B_) {
                int u = uIdx[r], s = sIdx[r];
                const float4* __restrict__ pa = (const float4*)(g_AB + u * H_);
                const float4* __restrict__ pb = (const float4*)(g_AB + (U_ + s) * H_);
#pragma unroll
                for (int q = 0; q < 16; q++) {
                    float4 a = pa[q];
                    float4 b = pb[q];
                    float v0 = a.x + b.x, v1 = a.y + b.y, v2 = a.z + b.z, v3 = a.w + b.w;
                    x[4 * q] = v0; x[4 * q + 1] = v1; x[4 * q + 2] = v2; x[4 * q + 3] = v3;
                    sum += v0 + v1 + v2 + v3;
                }
            } else {
#pragma unroll
                for (int k = 0; k < 64; k++) x[k] = 0.f;
            }
            float mu = sum * (1.f / 64.f);
            float var = 0.f;
#pragma unroll
            for (int k = 0; k < 64; k++) { float d = x[k] - mu; var += d * d; }
            float inv = rsqrtf(var * (1.f / 64.f) + EPS_);
#pragma unroll
            for (int q = 0; q < 16; q++) {
                uint4 w;
                w.x = to_tf32(fmaxf(0.f, (x[4 * q]     - mu) * inv * sg1[4 * q]     + sbe1[4 * q]));
                w.y = to_tf32(fmaxf(0.f, (x[4 * q + 1] - mu) * inv * sg1[4 * q + 1] + sbe1[4 * q + 1]));
                w.z = to_tf32(fmaxf(0.f, (x[4 * q + 2] - mu) * inv * sg1[4 * q + 2] + sbe1[4 * q + 2]));
                w.w = to_tf32(fmaxf(0.f, (x[4 * q + 3] - mu) * inv * sg1[4 * q + 3] + sbe1[4 * q + 3]));
                *(uint4*)(rowp + 4 * q) = w;
            }
        }
        __syncwarp();

#pragma unroll
        for (int mt = 0; mt < 2; mt++) {
            int mb = (wid * 2 + mt) * 16;
            const uint32_t* arow0 = sX + (mb + gid) * XS;
            const uint32_t* arow1 = sX + (mb + gid + 8) * XS;

            float c[8][4];
#pragma unroll
            for (int no = 0; no < 8; no++) {
                c[no][0] = 0.f; c[no][1] = 0.f; c[no][2] = 0.f; c[no][3] = 0.f;
            }
#pragma unroll
            for (int ko = 0; ko < 8; ko++) {
                int k0 = ko * 8;
                uint32_t a0 = arow0[k0 + tig];
                uint32_t a1 = arow1[k0 + tig];
                uint32_t a2 = arow0[k0 + tig + 4];
                uint32_t a3 = arow1[k0 + tig + 4];
                const uint32_t* bk0 = sW + (k0 + tig) * WS;
                const uint32_t* bk1 = sW + (k0 + tig + 4) * WS;
#pragma unroll
                for (int no = 0; no < 8; no++) {
                    uint32_t b0 = bk0[no * 8 + gid];
                    uint32_t b1 = bk1[no * 8 + gid];
                    mma16n8k8(c[no], a0, a1, a2, a3, b0, b1);
                }
            }

            float ep_g2[16], ep_be2[16], ep_w3[16];
            float s0 = 0.f, q0 = 0.f, s1 = 0.f, q1 = 0.f;
#pragma unroll
            for (int no = 0; no < 8; no++) {
                int col = no * 8 + 2 * tig;
                float4 e0 = sEp[col];
                float4 e1 = sEp[col + 1];
                ep_g2[2 * no] = e0.y;  ep_be2[2 * no] = e0.z;  ep_w3[2 * no] = e0.w;
                ep_g2[2 * no + 1] = e1.y; ep_be2[2 * no + 1] = e1.z; ep_w3[2 * no + 1] = e1.w;
                c[no][0] += e0.x; c[no][1] += e1.x;
                c[no][2] += e0.x; c[no][3] += e1.x;
                s0 += c[no][0] + c[no][1];
                q0 += c[no][0] * c[no][0] + c[no][1] * c[no][1];
                s1 += c[no][2] + c[no][3];
                q1 += c[no][2] * c[no][2] + c[no][3] * c[no][3];
            }
            s0 += __shfl_xor_sync(0xffffffffu, s0, 1);
            s0 += __shfl_xor_sync(0xffffffffu, s0, 2);
            q0 += __shfl_xor_sync(0xffffffffu, q0, 1);
            q0 += __shfl_xor_sync(0xffffffffu, q0, 2);
            s1 += __shfl_xor_sync(0xffffffffu, s1, 1);
            s1 += __shfl_xor_sync(0xffffffffu, s1, 2);
            q1 += __shfl_xor_sync(0xffffffffu, q1, 1);
            q1 += __shfl_xor_sync(0xffffffffu, q1, 2);

            float mu0 = s0 * (1.f / 64.f);
            float var0 = fmaxf(q0 * (1.f / 64.f) - mu0 * mu0, 0.f);
            float inv0 = rsqrtf(var0 + EPS_);
            float mu1 = s1 * (1.f / 64.f);
            float var1 = fmaxf(q1 * (1.f / 64.f) - mu1 * mu1, 0.f);
            float inv1 = rsqrtf(var1 + EPS_);

            float d0 = 0.f, d1 = 0.f;
#pragma unroll
            for (int no = 0; no < 8; no++) {
#pragma unroll
                for (int j = 0; j < 2; j++) {
                    int p = 2 * no + j;
                    float h0 = fmaxf(0.f, (c[no][j]     - mu0) * inv0 * ep_g2[p] + ep_be2[p]);
                    float h1 = fmaxf(0.f, (c[no][2 + j] - mu1) * inv1 * ep_g2[p] + ep_be2[p]);
                    d0 += h0 * ep_w3[p];
                    d1 += h1 * ep_w3[p];
                }
            }
            d0 += __shfl_xor_sync(0xffffffffu, d0, 1);
            d0 += __shfl_xor_sync(0xffffffffu, d0, 2);
            d1 += __shfl_xor_sync(0xffffffffu, d1, 1);
            d1 += __shfl_xor_sync(0xffffffffu, d1, 2);

            if (tig == 0) {
                int r0 = tile * 128 + mb + gid;
                int r1 = r0 + 8;
                if (r0 < B_) out[r0] = d0 + bb;
                if (r1 < B_) out[r1] = d1 + bb;
            }
        }
        __syncwarp();
    }
}

// ---------------- launcher ----------------
extern "C" void kernel_launch(void* const* d_in, const int* in_sizes, int n_in,
                              void* d_out, int out_size) {
    const float* uE  = (const float*)d_in[0];
    const float* iE  = (const float*)d_in[1];
    const float* uH  = (const float*)d_in[2];
    const float* iH  = (const float*)d_in[3];
    const float* W1  = (const float*)d_in[4];
    const float* b1  = (const float*)d_in[5];
    const float* g1  = (const float*)d_in[6];
    const float* be1 = (const float*)d_in[7];
    const float* W2  = (const float*)d_in[8];
    const float* b2  = (const float*)d_in[9];
    const float* g2  = (const float*)d_in[10];
    const float* be2 = (const float*)d_in[11];
    const float* W3  = (const float*)d_in[12];
    const float* b3  = (const float*)d_in[13];
    const float* adj_vals = (const float*)d_in[14];
    const int*   adj_rows = (const int*)d_in[15];
    const int*   adj_cols = (const int*)d_in[16];
    const int*   uIdx = (const int*)d_in[17];
    const int*   sIdx = (const int*)d_in[18];
    float* out = (float*)d_out;

    static int attr_set = 0;
    if (!attr_set) {
        cudaFuncSetAttribute(mlp_kernel, cudaFuncAttributeMaxDynamicSharedMemorySize,
                             128 * XS * 4);
        attr_set = 1;
    }

    prep_hist_kernel<<<HB2, HT2>>>(uE, iE, adj_rows);
    scan_hyperQ_kernel<<<3, 1024>>>(uH, iH, W1);
    scatter_kernel<<<HB2, HT2>>>(adj_rows, adj_cols, adj_vals);
    spmm_kernel<<<U_ + SPMM_SBLKS, 256>>>(0);   // e1 = A e0  (A -> B)
    spmm_kernel<<<U_ + SPMM_SBLKS, 256>>>(1);   // e2 = A e1  (B -> A)
    projP_kernel<<<(N_ + 31) / 32, 256>>>();    // P = e2 @ Q_swapped
    spmm64_kernel<<<U_ + SPMM_SBLKS, 256>>>(b1);// AB = A @ P (+b1)
    mlp_kernel<<<MLP_GRID, 128, 128 * XS * 4>>>(uIdx, sIdx, g1, be1, W2, b2,
                                                g2, be2, W3, b3, out);
}